// round 3
// baseline (speedup 1.0000x reference)
#include <cuda_runtime.h>
#include <math.h>

// Problem constants
#define CIN    64
#define HH     256
#define WW     256
#define COUT   64
#define NHD    8      // heads per (b,t)
#define HG     32
#define WG     32
#define NQ     1024   // tokens per head (Hg*Wg)
#define DDIM   512    // head dim (hc * 8 * 8)
#define NBT    8      // B*T
#define NHEADS 64     // NBT * NHD
#define KCONV  576    // CIN*9
#define ATT_SCALE 0.044194173824159216f  // 1/sqrt(512)

// Scratch (device globals; no allocations allowed).
// NOTE: g_Q is reused as the attention-output image buffer after qk_kernel
// (both are exactly NHEADS*NQ*DDIM == NBT*COUT*HH*WW == 33.5M floats).
__device__ float g_Q[NHEADS * NQ * DDIM];          // 134 MB (later: image buf)
__device__ float g_K[NHEADS * NQ * DDIM];          // 134 MB
__device__ float g_V[NHEADS * NQ * DDIM];          // 134 MB
__device__ float g_S[NHEADS * NQ * NQ];            // 268 MB

// ---------------------------------------------------------------------------
// Kernel 1: fused QKV grid-conv.
// Each block: one conv (blockIdx.y in {q,k,v}), 16 grid-samples.
// A grid-sample (bt,hi,wi) is a 64ch x 8x8 image; 3x3 'same' conv -> 64ch x 8x8.
// Patch staged padded (10x10) in smem; weights staged in 8-ci chunks.
// Thread: 1 position (gi,gj) x 8 output channels.
// ---------------------------------------------------------------------------
__global__ __launch_bounds__(512) void qkv_conv_kernel(
    const float* __restrict__ x,
    const float* __restrict__ wq, const float* __restrict__ bq,
    const float* __restrict__ wk, const float* __restrict__ bk,
    const float* __restrict__ wv, const float* __restrict__ bv)
{
    __shared__ float Wc[72 * 68];      // [kl=ci_l*9+dd][co], row pad 68
    __shared__ float patch[64 * 100];  // [ci][10][10] zero-padded halo

    const int conv = blockIdx.y;
    const float* wsrc = (conv == 0) ? wq : (conv == 1) ? wk : wv;
    const float* bsrc = (conv == 0) ? bq : (conv == 1) ? bk : bv;
    float* dst = (conv == 0) ? g_Q : (conv == 1) ? g_K : g_V;

    const int tid = threadIdx.x;
    const int cog = tid >> 6;            // 0..7
    const int pos = tid & 63;            // gi*8+gj
    const int gi  = pos >> 3, gj = pos & 7;
    const int co0 = cog * 8;

    float bias[8];
#pragma unroll
    for (int i = 0; i < 8; i++) bias[i] = bsrc[co0 + i];

    const int s0 = blockIdx.x * 16;
    for (int si = 0; si < 16; si++) {
        const int s  = s0 + si;
        const int bt = s >> 10;
        const int q  = s & 1023;
        const int hi = q >> 5, wi = q & 31;

        __syncthreads();   // previous sample's compute done before patch overwrite
        for (int i = tid; i < 64 * 100; i += 512) patch[i] = 0.f;
        __syncthreads();
        for (int i = tid; i < 64 * 64; i += 512) {
            const int ci = i >> 6, p = i & 63;
            const int pgi = p >> 3, pgj = p & 7;
            patch[ci * 100 + (pgi + 1) * 10 + (pgj + 1)] =
                x[((bt * CIN + ci) * HH + (pgi * HG + hi)) * WW + (pgj * WG + wi)];
        }

        float acc[8];
#pragma unroll
        for (int i = 0; i < 8; i++) acc[i] = bias[i];

        for (int cc = 0; cc < 8; cc++) {
            const int ci0 = cc * 8;
            __syncthreads();   // prev chunk compute done; also publishes patch stores (cc==0)
            for (int i = tid; i < 4608; i += 512) {
                const int co_s = i / 72;
                const int kl_s = i - co_s * 72;
                Wc[kl_s * 68 + co_s] = wsrc[co_s * KCONV + ci0 * 9 + kl_s];
            }
            __syncthreads();
#pragma unroll
            for (int dy = 0; dy < 3; dy++) {
#pragma unroll
                for (int dx = 0; dx < 3; dx++) {
                    const float* prow = &patch[ci0 * 100 + (gi + dy) * 10 + (gj + dx)];
                    const float* wrow = &Wc[(dy * 3 + dx) * 68 + co0];
#pragma unroll
                    for (int cl = 0; cl < 8; cl++) {
                        const float p = prow[cl * 100];
                        const float4 w0 = *(const float4*)&wrow[cl * 9 * 68];
                        const float4 w1 = *(const float4*)&wrow[cl * 9 * 68 + 4];
                        acc[0] += w0.x * p; acc[1] += w0.y * p;
                        acc[2] += w0.z * p; acc[3] += w0.w * p;
                        acc[4] += w1.x * p; acc[5] += w1.y * p;
                        acc[6] += w1.z * p; acc[7] += w1.w * p;
                    }
                }
            }
        }
        // Write in attention layout: dst[head][q][d], d = cl*64 + gi*8 + gj
#pragma unroll
        for (int i = 0; i < 8; i++) {
            const int co = co0 + i;
            const int n = co >> 3, cl = co & 7;
            dst[((bt * NHD + n) * NQ + q) * DDIM + cl * 64 + pos] = acc[i];
        }
    }
}

// ---------------------------------------------------------------------------
// Kernel 2: S = scale * Q @ K^T   (batched over 64 heads, 1024x1024, K=512)
// 64x64 tile, 256 threads, 4x4 micro-tile, 16-wide K chunks.
// ---------------------------------------------------------------------------
__global__ __launch_bounds__(256) void qk_kernel()
{
    __shared__ float As[16][68];
    __shared__ float Bs[16][68];
    const int h  = blockIdx.z;
    const int m0 = blockIdx.y * 64;
    const int n0 = blockIdx.x * 64;
    const float* A = g_Q + (size_t)h * NQ * DDIM;
    const float* B = g_K + (size_t)h * NQ * DDIM;
    float* C = g_S + (size_t)h * NQ * NQ;

    const int tid = threadIdx.x;
    const int tm = (tid & 15) * 4;
    const int tn = (tid >> 4) * 4;
    const int lr = tid >> 2;          // 0..63 tile row for loads
    const int lk = (tid & 3) * 4;     // 0,4,8,12

    float acc[4][4];
#pragma unroll
    for (int i = 0; i < 4; i++)
#pragma unroll
        for (int j = 0; j < 4; j++) acc[i][j] = 0.f;

    for (int kc = 0; kc < DDIM; kc += 16) {
        const float4 a = *(const float4*)&A[(size_t)(m0 + lr) * DDIM + kc + lk];
        const float4 b = *(const float4*)&B[(size_t)(n0 + lr) * DDIM + kc + lk];
        __syncthreads();
        As[lk + 0][lr] = a.x; As[lk + 1][lr] = a.y; As[lk + 2][lr] = a.z; As[lk + 3][lr] = a.w;
        Bs[lk + 0][lr] = b.x; Bs[lk + 1][lr] = b.y; Bs[lk + 2][lr] = b.z; Bs[lk + 3][lr] = b.w;
        __syncthreads();
#pragma unroll
        for (int kk = 0; kk < 16; kk++) {
            const float4 av = *(const float4*)&As[kk][tm];
            const float4 bv = *(const float4*)&Bs[kk][tn];
            acc[0][0] += av.x * bv.x; acc[0][1] += av.x * bv.y; acc[0][2] += av.x * bv.z; acc[0][3] += av.x * bv.w;
            acc[1][0] += av.y * bv.x; acc[1][1] += av.y * bv.y; acc[1][2] += av.y * bv.z; acc[1][3] += av.y * bv.w;
            acc[2][0] += av.z * bv.x; acc[2][1] += av.z * bv.y; acc[2][2] += av.z * bv.z; acc[2][3] += av.z * bv.w;
            acc[3][0] += av.w * bv.x; acc[3][1] += av.w * bv.y; acc[3][2] += av.w * bv.z; acc[3][3] += av.w * bv.w;
        }
    }
#pragma unroll
    for (int i = 0; i < 4; i++)
#pragma unroll
        for (int j = 0; j < 4; j++)
            C[(size_t)(m0 + tm + i) * NQ + (n0 + tn + j)] = acc[i][j] * ATT_SCALE;
}

// ---------------------------------------------------------------------------
// Kernel 3: row softmax over g_S, in place. One block per 4 rows (looped).
// ---------------------------------------------------------------------------
__global__ __launch_bounds__(256) void softmax_kernel()
{
    __shared__ float redm[8];
    __shared__ float reds[8];
    const int tid = threadIdx.x;
    for (int r = 0; r < 4; r++) {
        float* S = g_S + (size_t)(blockIdx.x * 4 + r) * NQ;
        float v0 = S[tid], v1 = S[tid + 256], v2 = S[tid + 512], v3 = S[tid + 768];
        float m = fmaxf(fmaxf(v0, v1), fmaxf(v2, v3));
#pragma unroll
        for (int o = 16; o > 0; o >>= 1) m = fmaxf(m, __shfl_xor_sync(0xffffffffu, m, o));
        if ((tid & 31) == 0) redm[tid >> 5] = m;
        __syncthreads();
        m = redm[0];
#pragma unroll
        for (int i = 1; i < 8; i++) m = fmaxf(m, redm[i]);
        v0 = __expf(v0 - m); v1 = __expf(v1 - m); v2 = __expf(v2 - m); v3 = __expf(v3 - m);
        float sum = v0 + v1 + v2 + v3;
#pragma unroll
        for (int o = 16; o > 0; o >>= 1) sum += __shfl_xor_sync(0xffffffffu, sum, o);
        if ((tid & 31) == 0) reds[tid >> 5] = sum;
        __syncthreads();
        sum = 0.f;
#pragma unroll
        for (int i = 0; i < 8; i++) sum += reds[i];
        const float inv = 1.0f / sum;
        S[tid] = v0 * inv; S[tid + 256] = v1 * inv; S[tid + 512] = v2 * inv; S[tid + 768] = v3 * inv;
        __syncthreads();   // reds/redm reuse across iterations
    }
}

// ---------------------------------------------------------------------------
// Kernel 4: Y = P @ V (batched, 1024x512, K=1024), epilogue fuses grid2im
// scatter into the image buffer (aliased onto g_Q, which is dead by now).
// ---------------------------------------------------------------------------
__global__ __launch_bounds__(256) void pv_kernel()
{
    __shared__ float As[16][68];
    __shared__ float Bs[16][68];
    const int h  = blockIdx.z;
    const int m0 = blockIdx.y * 64;
    const int n0 = blockIdx.x * 64;
    const float* A = g_S + (size_t)h * NQ * NQ;
    const float* B = g_V + (size_t)h * NQ * DDIM;
    float* img = g_Q;   // reuse: g_Q consumed by qk_kernel already

    const int tid = threadIdx.x;
    const int tm = (tid & 15) * 4;
    const int tn = (tid >> 4) * 4;
    const int lr = tid >> 2;
    const int lk = (tid & 3) * 4;
    const int bk = tid >> 4;          // 0..15 (k row of B chunk)
    const int bn = (tid & 15) * 4;    // n col of B chunk

    float acc[4][4];
#pragma unroll
    for (int i = 0; i < 4; i++)
#pragma unroll
        for (int j = 0; j < 4; j++) acc[i][j] = 0.f;

    for (int kc = 0; kc < NQ; kc += 16) {
        const float4 a = *(const float4*)&A[(size_t)(m0 + lr) * NQ + kc + lk];
        const float4 b = *(const float4*)&B[(size_t)(kc + bk) * DDIM + n0 + bn];
        __syncthreads();
        As[lk + 0][lr] = a.x; As[lk + 1][lr] = a.y; As[lk + 2][lr] = a.z; As[lk + 3][lr] = a.w;
        *(float4*)&Bs[bk][bn] = b;
        __syncthreads();
#pragma unroll
        for (int kk = 0; kk < 16; kk++) {
            const float4 av = *(const float4*)&As[kk][tm];
            const float4 bv = *(const float4*)&Bs[kk][tn];
            acc[0][0] += av.x * bv.x; acc[0][1] += av.x * bv.y; acc[0][2] += av.x * bv.z; acc[0][3] += av.x * bv.w;
            acc[1][0] += av.y * bv.x; acc[1][1] += av.y * bv.y; acc[1][2] += av.y * bv.z; acc[1][3] += av.y * bv.w;
            acc[2][0] += av.z * bv.x; acc[2][1] += av.z * bv.y; acc[2][2] += av.z * bv.z; acc[2][3] += av.z * bv.w;
            acc[3][0] += av.w * bv.x; acc[3][1] += av.w * bv.y; acc[3][2] += av.w * bv.z; acc[3][3] += av.w * bv.w;
        }
    }
    // grid2im scatter: img[bt][co][pgi*32+hi][pgj*32+wi] = Y[head][q][d]
    const int bt = h >> 3, nh = h & 7;
#pragma unroll
    for (int i = 0; i < 4; i++) {
        const int q  = m0 + tm + i;
        const int hi = q >> 5, wi = q & 31;
#pragma unroll
        for (int j = 0; j < 4; j++) {
            const int d = n0 + tn + j;
            const int cl = d >> 6, r = d & 63;
            const int pgi = r >> 3, pgj = r & 7;
            const int co = nh * 8 + cl;
            img[((bt * COUT + co) * HH + (pgi * HG + hi)) * WW + (pgj * WG + wi)] = acc[i][j];
        }
    }
}

// ---------------------------------------------------------------------------
// Kernel 5: out = img + conv3x3(img, wo) + bo  (full 256x256 image, per bt)
// Block: 16h x 32w spatial tile, 8 output channels; ci chunked by 8.
// ---------------------------------------------------------------------------
__global__ __launch_bounds__(256) void oconv_kernel(
    const float* __restrict__ wo, const float* __restrict__ bo,
    float* __restrict__ out)
{
    __shared__ float patch[8 * 18 * 34];   // [ci][18][34] halo tile
    __shared__ float Ws[72 * 8];           // [ci*9+dd][co]

    const int bz  = blockIdx.z;
    const int bt  = bz >> 3;
    const int co0 = (bz & 7) * 8;
    const int h0  = blockIdx.y * 16;
    const int w0  = blockIdx.x * 32;

    const int tid = threadIdx.x;
    const int th  = tid >> 4;     // 0..15
    const int tw  = tid & 15;     // covers tw and tw+16

    float acc[16];
#pragma unroll
    for (int i = 0; i < 16; i++) acc[i] = 0.f;

    const float* img = g_Q + (size_t)bt * COUT * HH * WW;   // aliased image buf

    for (int cc = 0; cc < 8; cc++) {
        const int ci0 = cc * 8;
        __syncthreads();
        for (int i = tid; i < 8 * 18 * 34; i += 256) {
            const int ci = i / 612;
            const int rem = i - ci * 612;
            const int r = rem / 34;
            const int c = rem - r * 34;
            const int gh = h0 - 1 + r, gw = w0 - 1 + c;
            float v = 0.f;
            if (gh >= 0 && gh < HH && gw >= 0 && gw < WW)
                v = img[((ci0 + ci) * HH + gh) * WW + gw];
            patch[i] = v;
        }
        for (int i = tid; i < 576; i += 256) {
            const int co = i / 72;
            const int rem = i - co * 72;
            Ws[rem * 8 + co] = wo[(co0 + co) * KCONV + ci0 * 9 + rem];
        }
        __syncthreads();
#pragma unroll
        for (int dy = 0; dy < 3; dy++) {
#pragma unroll
            for (int dx = 0; dx < 3; dx++) {
#pragma unroll
                for (int ci = 0; ci < 8; ci++) {
                    const float p0 = patch[ci * 612 + (th + dy) * 34 + (tw + dx)];
                    const float p1 = patch[ci * 612 + (th + dy) * 34 + (tw + 16 + dx)];
                    const float4 wa = *(const float4*)&Ws[(ci * 9 + dy * 3 + dx) * 8 + 0];
                    const float4 wb = *(const float4*)&Ws[(ci * 9 + dy * 3 + dx) * 8 + 4];
                    acc[0]  += wa.x * p0; acc[1]  += wa.x * p1;
                    acc[2]  += wa.y * p0; acc[3]  += wa.y * p1;
                    acc[4]  += wa.z * p0; acc[5]  += wa.z * p1;
                    acc[6]  += wa.w * p0; acc[7]  += wa.w * p1;
                    acc[8]  += wb.x * p0; acc[9]  += wb.x * p1;
                    acc[10] += wb.y * p0; acc[11] += wb.y * p1;
                    acc[12] += wb.z * p0; acc[13] += wb.z * p1;
                    acc[14] += wb.w * p0; acc[15] += wb.w * p1;
                }
            }
        }
    }
#pragma unroll
    for (int i = 0; i < 8; i++) {
        const int co = co0 + i;
        const float b = bo[co];
        const size_t o0 = ((size_t)(bt * COUT + co) * HH + (h0 + th)) * WW + (w0 + tw);
        const float c0 = img[(co * HH + h0 + th) * WW + w0 + tw];
        const float c1 = img[(co * HH + h0 + th) * WW + w0 + tw + 16];
        out[o0]      = acc[i * 2 + 0] + b + c0;
        out[o0 + 16] = acc[i * 2 + 1] + b + c1;
    }
}

// ---------------------------------------------------------------------------
extern "C" void kernel_launch(void* const* d_in, const int* in_sizes, int n_in,
                              void* d_out, int out_size)
{
    (void)in_sizes; (void)n_in; (void)out_size;
    const float* x  = (const float*)d_in[0];
    const float* wq = (const float*)d_in[1];
    const float* bq = (const float*)d_in[2];
    const float* wk = (const float*)d_in[3];
    const float* bk = (const float*)d_in[4];
    const float* wv = (const float*)d_in[5];
    const float* bv = (const float*)d_in[6];
    const float* wo = (const float*)d_in[7];
    const float* bo = (const float*)d_in[8];
    float* out = (float*)d_out;

    qkv_conv_kernel<<<dim3(512, 3), 512>>>(x, wq, bq, wk, bk, wv, bv);
    qk_kernel<<<dim3(16, 16, 64), 256>>>();
    softmax_kernel<<<16384, 256>>>();
    pv_kernel<<<dim3(8, 16, 64), 256>>>();
    oconv_kernel<<<dim3(8, 16, 64), 256>>>(wo, bo, out);
}

// round 6
// speedup vs baseline: 1.3939x; 1.3939x over previous
#include <cuda_runtime.h>
#include <math.h>

// Problem constants
#define CIN    64
#define HH     256
#define WW     256
#define COUT   64
#define NHD    8
#define HG     32
#define WG     32
#define NQ     1024
#define DDIM   512
#define NBT    8
#define NHEADS 64
#define KCONV  576
#define ATT_SCALE 0.044194173824159216f  // 1/sqrt(512)

// Scratch (device globals). g_Q is reused as the attention-output image buffer
// after qk_kernel (both are exactly 33.5M floats).
__device__ float g_Q[NHEADS * NQ * DDIM];
__device__ float g_K[NHEADS * NQ * DDIM];
__device__ float g_V[NHEADS * NQ * DDIM];
__device__ float g_S[NHEADS * NQ * NQ];

// ---------------------------------------------------------------------------
// Kernel 1: fused QKV grid-conv.
// Block = 512 threads = 4 samples x (8 co-groups x 16 pos-threads).
// Thread: 4 consecutive positions x 8 output channels (32 acc).
// Per ci-chunk (8 ci): weights staged once for all 4 samples; patch staged
// per-chunk per-sample ([s][cil][10x10] with zero halo).
// ---------------------------------------------------------------------------
__global__ __launch_bounds__(512) void qkv_conv_kernel(
    const float* __restrict__ x,
    const float* __restrict__ wq, const float* __restrict__ bq,
    const float* __restrict__ wk, const float* __restrict__ bk,
    const float* __restrict__ wv, const float* __restrict__ bv)
{
    __shared__ float Wc[72 * 68];         // [kl = cil*9+dd][co], pad 68
    __shared__ float pat[4][8][100];      // [s][cil][10x10], halo stays zero

    const int conv = blockIdx.y;
    const float* wsrc = (conv == 0) ? wq : (conv == 1) ? wk : wv;
    const float* bsrc = (conv == 0) ? bq : (conv == 1) ? bk : bv;
    float* dst = (conv == 0) ? g_Q : (conv == 1) ? g_K : g_V;

    const int tid = threadIdx.x;
    const int s   = tid >> 7;          // sample in group 0..3
    const int t2  = tid & 127;
    const int cog = t2 >> 4;           // 0..7 (co0 = cog*8)
    const int pt  = t2 & 15;           // position quad: p = 4*pt + u
    const int gi  = pt >> 1;
    const int gjb = (pt & 1) * 4;
    const int co0 = cog * 8;

    float bias[8];
#pragma unroll
    for (int i = 0; i < 8; i++) bias[i] = bsrc[co0 + i];

    // zero patch buffers once (halo cells are never rewritten)
    for (int i = tid; i < 4 * 8 * 100; i += 512) ((float*)pat)[i] = 0.f;

    for (int g = 0; g < 8; g++) {
        const int qbase = blockIdx.x * 32 + g * 4;   // 4-aligned => same hi
        const int sg = qbase + s;
        const int bt = sg >> 10;
        const int q  = sg & 1023;
        const int hi = q >> 5, wi = q & 31;

        float acc[8][4];
#pragma unroll
        for (int i = 0; i < 8; i++)
#pragma unroll
            for (int u = 0; u < 4; u++) acc[i][u] = bias[i];

        for (int cc = 0; cc < 8; cc++) {
            __syncthreads();   // prev compute (or zero fill) done
            // stage weight chunk: Wc[kl][co] = w[co][cc*8+cil][dy][dx]
            for (int i = tid; i < 4608; i += 512) {
                const int co_s = i / 72;
                const int kl   = i - co_s * 72;
                Wc[kl * 68 + co_s] = wsrc[co_s * KCONV + cc * 72 + kl];
            }
            // stage patch interiors: i = ((cil*8+pgi)*8+pgj)*4 + ss
            for (int i = tid; i < 2048; i += 512) {
                const int ss  = i & 3;
                int r = i >> 2;
                const int pgj = r & 7; r >>= 3;
                const int pgi = r & 7;
                const int cil = r >> 3;
                const int sg2 = qbase + ss;
                const int bt2 = sg2 >> 10;
                const int q2  = sg2 & 1023;
                const int hi2 = q2 >> 5, wi2 = q2 & 31;
                pat[ss][cil][(pgi + 1) * 10 + pgj + 1] =
                    x[((bt2 * CIN + cc * 8 + cil) * HH + (pgi * HG + hi2)) * WW + pgj * WG + wi2];
            }
            __syncthreads();
#pragma unroll
            for (int dy = 0; dy < 3; dy++) {
#pragma unroll
                for (int dx = 0; dx < 3; dx++) {
#pragma unroll
                    for (int cl = 0; cl < 8; cl++) {
                        const float* prow = &pat[s][cl][(gi + dy) * 10 + gjb + dx];
                        const float p0 = prow[0], p1 = prow[1], p2 = prow[2], p3 = prow[3];
                        const float* wrow = &Wc[(cl * 9 + dy * 3 + dx) * 68 + co0];
                        const float4 w0 = *(const float4*)&wrow[0];
                        const float4 w1 = *(const float4*)&wrow[4];
                        acc[0][0] += w0.x * p0; acc[0][1] += w0.x * p1; acc[0][2] += w0.x * p2; acc[0][3] += w0.x * p3;
                        acc[1][0] += w0.y * p0; acc[1][1] += w0.y * p1; acc[1][2] += w0.y * p2; acc[1][3] += w0.y * p3;
                        acc[2][0] += w0.z * p0; acc[2][1] += w0.z * p1; acc[2][2] += w0.z * p2; acc[2][3] += w0.z * p3;
                        acc[3][0] += w0.w * p0; acc[3][1] += w0.w * p1; acc[3][2] += w0.w * p2; acc[3][3] += w0.w * p3;
                        acc[4][0] += w1.x * p0; acc[4][1] += w1.x * p1; acc[4][2] += w1.x * p2; acc[4][3] += w1.x * p3;
                        acc[5][0] += w1.y * p0; acc[5][1] += w1.y * p1; acc[5][2] += w1.y * p2; acc[5][3] += w1.y * p3;
                        acc[6][0] += w1.z * p0; acc[6][1] += w1.z * p1; acc[6][2] += w1.z * p2; acc[6][3] += w1.z * p3;
                        acc[7][0] += w1.w * p0; acc[7][1] += w1.w * p1; acc[7][2] += w1.w * p2; acc[7][3] += w1.w * p3;
                    }
                }
            }
        }
        // write: co = co0+i -> head n=cog, cl=i; d = cl*64 + (4*pt+u)
        float* drow = &dst[((size_t)(bt * NHD + cog) * NQ + q) * DDIM + pt * 4];
#pragma unroll
        for (int i = 0; i < 8; i++) {
            float4 v = make_float4(acc[i][0], acc[i][1], acc[i][2], acc[i][3]);
            *(float4*)&drow[i * 64] = v;
        }
    }
}

// ---------------------------------------------------------------------------
// Kernel 2: S = scale * Q @ K^T. 128x128 tile, BK=16, 256 thr, 8x8 microtile.
// ---------------------------------------------------------------------------
__global__ __launch_bounds__(256) void qk_kernel()
{
    __shared__ float As[16][132];
    __shared__ float Bs[16][132];
    const int h  = blockIdx.z;
    const int m0 = blockIdx.y * 128;
    const int n0 = blockIdx.x * 128;
    const float* A = g_Q + (size_t)h * NQ * DDIM;
    const float* B = g_K + (size_t)h * NQ * DDIM;
    float* C = g_S + (size_t)h * NQ * NQ;

    const int tid = threadIdx.x;
    const int lr = tid >> 2;             // 0..63
    const int lc = (tid & 3) * 4;        // 0,4,8,12
    const int tx = tid & 15, ty = tid >> 4;

    float acc[8][8];
#pragma unroll
    for (int i = 0; i < 8; i++)
#pragma unroll
        for (int j = 0; j < 8; j++) acc[i][j] = 0.f;

    for (int kc = 0; kc < DDIM; kc += 16) {
        const float4 a0 = *(const float4*)&A[(size_t)(m0 + lr) * DDIM + kc + lc];
        const float4 a1 = *(const float4*)&A[(size_t)(m0 + lr + 64) * DDIM + kc + lc];
        const float4 b0 = *(const float4*)&B[(size_t)(n0 + lr) * DDIM + kc + lc];
        const float4 b1 = *(const float4*)&B[(size_t)(n0 + lr + 64) * DDIM + kc + lc];
        __syncthreads();
        As[lc + 0][lr] = a0.x; As[lc + 1][lr] = a0.y; As[lc + 2][lr] = a0.z; As[lc + 3][lr] = a0.w;
        As[lc + 0][lr + 64] = a1.x; As[lc + 1][lr + 64] = a1.y; As[lc + 2][lr + 64] = a1.z; As[lc + 3][lr + 64] = a1.w;
        Bs[lc + 0][lr] = b0.x; Bs[lc + 1][lr] = b0.y; Bs[lc + 2][lr] = b0.z; Bs[lc + 3][lr] = b0.w;
        Bs[lc + 0][lr + 64] = b1.x; Bs[lc + 1][lr + 64] = b1.y; Bs[lc + 2][lr + 64] = b1.z; Bs[lc + 3][lr + 64] = b1.w;
        __syncthreads();
#pragma unroll
        for (int kk = 0; kk < 16; kk++) {
            const float4 av0 = *(const float4*)&As[kk][ty * 4];
            const float4 av1 = *(const float4*)&As[kk][ty * 4 + 64];
            const float4 bv0 = *(const float4*)&Bs[kk][tx * 4];
            const float4 bv1 = *(const float4*)&Bs[kk][tx * 4 + 64];
            const float am[8] = {av0.x, av0.y, av0.z, av0.w, av1.x, av1.y, av1.z, av1.w};
            const float bn[8] = {bv0.x, bv0.y, bv0.z, bv0.w, bv1.x, bv1.y, bv1.z, bv1.w};
#pragma unroll
            for (int i = 0; i < 8; i++)
#pragma unroll
                for (int j = 0; j < 8; j++) acc[i][j] += am[i] * bn[j];
        }
    }
#pragma unroll
    for (int i = 0; i < 8; i++) {
        const int m = m0 + ((i < 4) ? (ty * 4 + i) : (64 + ty * 4 + i - 4));
        float4 v0 = make_float4(acc[i][0] * ATT_SCALE, acc[i][1] * ATT_SCALE,
                                acc[i][2] * ATT_SCALE, acc[i][3] * ATT_SCALE);
        float4 v1 = make_float4(acc[i][4] * ATT_SCALE, acc[i][5] * ATT_SCALE,
                                acc[i][6] * ATT_SCALE, acc[i][7] * ATT_SCALE);
        *(float4*)&C[(size_t)m * NQ + n0 + tx * 4] = v0;
        *(float4*)&C[(size_t)m * NQ + n0 + 64 + tx * 4] = v1;
    }
}

// ---------------------------------------------------------------------------
// Kernel 3: row softmax over g_S, in place. One block per 4 rows.
// ---------------------------------------------------------------------------
__global__ __launch_bounds__(256) void softmax_kernel()
{
    __shared__ float redm[8];
    __shared__ float reds[8];
    const int tid = threadIdx.x;
    for (int r = 0; r < 4; r++) {
        float* S = g_S + (size_t)(blockIdx.x * 4 + r) * NQ;
        float v0 = S[tid], v1 = S[tid + 256], v2 = S[tid + 512], v3 = S[tid + 768];
        float m = fmaxf(fmaxf(v0, v1), fmaxf(v2, v3));
#pragma unroll
        for (int o = 16; o > 0; o >>= 1) m = fmaxf(m, __shfl_xor_sync(0xffffffffu, m, o));
        if ((tid & 31) == 0) redm[tid >> 5] = m;
        __syncthreads();
        m = redm[0];
#pragma unroll
        for (int i = 1; i < 8; i++) m = fmaxf(m, redm[i]);
        v0 = __expf(v0 - m); v1 = __expf(v1 - m); v2 = __expf(v2 - m); v3 = __expf(v3 - m);
        float sum = v0 + v1 + v2 + v3;
#pragma unroll
        for (int o = 16; o > 0; o >>= 1) sum += __shfl_xor_sync(0xffffffffu, sum, o);
        if ((tid & 31) == 0) reds[tid >> 5] = sum;
        __syncthreads();
        sum = 0.f;
#pragma unroll
        for (int i = 0; i < 8; i++) sum += reds[i];
        const float inv = 1.0f / sum;
        S[tid] = v0 * inv; S[tid + 256] = v1 * inv; S[tid + 512] = v2 * inv; S[tid + 768] = v3 * inv;
        __syncthreads();
    }
}

// ---------------------------------------------------------------------------
// Kernel 4: Y = P @ V. 128x128 tile, BK=16, 256 thr, 8x8 microtile.
// Epilogue fuses grid2im scatter into image buffer (aliased g_Q).
// ---------------------------------------------------------------------------
__global__ __launch_bounds__(256) void pv_kernel()
{
    __shared__ float As[16][132];
    __shared__ float Bs[16][132];
    const int h  = blockIdx.z;
    const int m0 = blockIdx.y * 128;
    const int n0 = blockIdx.x * 128;
    const float* A = g_S + (size_t)h * NQ * NQ;
    const float* B = g_V + (size_t)h * NQ * DDIM;
    float* img = g_Q;   // g_Q dead after qk_kernel

    const int tid = threadIdx.x;
    const int lr = tid >> 2;
    const int lc = (tid & 3) * 4;
    const int br = tid >> 5;             // 0..7
    const int bc = (tid & 31) * 4;       // 0..124
    const int tx = tid & 15, ty = tid >> 4;

    float acc[8][8];
#pragma unroll
    for (int i = 0; i < 8; i++)
#pragma unroll
        for (int j = 0; j < 8; j++) acc[i][j] = 0.f;

    for (int kc = 0; kc < NQ; kc += 16) {
        const float4 a0 = *(const float4*)&A[(size_t)(m0 + lr) * NQ + kc + lc];
        const float4 a1 = *(const float4*)&A[(size_t)(m0 + lr + 64) * NQ + kc + lc];
        const float4 bA = *(const float4*)&B[(size_t)(kc + br) * DDIM + n0 + bc];
        const float4 bB = *(const float4*)&B[(size_t)(kc + br + 8) * DDIM + n0 + bc];
        __syncthreads();
        As[lc + 0][lr] = a0.x; As[lc + 1][lr] = a0.y; As[lc + 2][lr] = a0.z; As[lc + 3][lr] = a0.w;
        As[lc + 0][lr + 64] = a1.x; As[lc + 1][lr + 64] = a1.y; As[lc + 2][lr + 64] = a1.z; As[lc + 3][lr + 64] = a1.w;
        *(float4*)&Bs[br][bc] = bA;
        *(float4*)&Bs[br + 8][bc] = bB;
        __syncthreads();
#pragma unroll
        for (int kk = 0; kk < 16; kk++) {
            const float4 av0 = *(const float4*)&As[kk][ty * 4];
            const float4 av1 = *(const float4*)&As[kk][ty * 4 + 64];
            const float4 bv0 = *(const float4*)&Bs[kk][tx * 4];
            const float4 bv1 = *(const float4*)&Bs[kk][tx * 4 + 64];
            const float am[8] = {av0.x, av0.y, av0.z, av0.w, av1.x, av1.y, av1.z, av1.w};
            const float bn[8] = {bv0.x, bv0.y, bv0.z, bv0.w, bv1.x, bv1.y, bv1.z, bv1.w};
#pragma unroll
            for (int i = 0; i < 8; i++)
#pragma unroll
                for (int j = 0; j < 8; j++) acc[i][j] += am[i] * bn[j];
        }
    }
    // grid2im scatter
    const int bt = h >> 3, nh = h & 7;
#pragma unroll
    for (int i = 0; i < 8; i++) {
        const int q  = m0 + ((i < 4) ? (ty * 4 + i) : (64 + ty * 4 + i - 4));
        const int hi = q >> 5, wi = q & 31;
#pragma unroll
        for (int j = 0; j < 8; j++) {
            const int d = n0 + ((j < 4) ? (tx * 4 + j) : (64 + tx * 4 + j - 4));
            const int cl = d >> 6, r = d & 63;
            const int pgi = r >> 3, pgj = r & 7;
            const int co = nh * 8 + cl;
            img[((bt * COUT + co) * HH + (pgi * HG + hi)) * WW + (pgj * WG + wi)] = acc[i][j];
        }
    }
}

// ---------------------------------------------------------------------------
// Kernel 5: out = img + conv3x3(img, wo) + bo
// ---------------------------------------------------------------------------
__global__ __launch_bounds__(256) void oconv_kernel(
    const float* __restrict__ wo, const float* __restrict__ bo,
    float* __restrict__ out)
{
    __shared__ float patch[8 * 18 * 34];
    __shared__ float Ws[72 * 8];

    const int bz  = blockIdx.z;
    const int bt  = bz >> 3;
    const int co0 = (bz & 7) * 8;
    const int h0  = blockIdx.y * 16;
    const int w0  = blockIdx.x * 32;

    const int tid = threadIdx.x;
    const int th  = tid >> 4;
    const int tw  = tid & 15;

    float acc[16];
#pragma unroll
    for (int i = 0; i < 16; i++) acc[i] = 0.f;

    const float* img = g_Q + (size_t)bt * COUT * HH * WW;

    for (int cc = 0; cc < 8; cc++) {
        const int ci0 = cc * 8;
        __syncthreads();
        for (int i = tid; i < 8 * 18 * 34; i += 256) {
            const int ci = i / 612;
            const int rem = i - ci * 612;
            const int r = rem / 34;
            const int c = rem - r * 34;
            const int gh = h0 - 1 + r, gw = w0 - 1 + c;
            float v = 0.f;
            if (gh >= 0 && gh < HH && gw >= 0 && gw < WW)
                v = img[((ci0 + ci) * HH + gh) * WW + gw];
            patch[i] = v;
        }
        for (int i = tid; i < 576; i += 256) {
            const int co = i / 72;
            const int rem = i - co * 72;
            Ws[rem * 8 + co] = wo[(co0 + co) * KCONV + ci0 * 9 + rem];
        }
        __syncthreads();
#pragma unroll
        for (int dy = 0; dy < 3; dy++) {
#pragma unroll
            for (int dx = 0; dx < 3; dx++) {
#pragma unroll
                for (int ci = 0; ci < 8; ci++) {
                    const float p0 = patch[ci * 612 + (th + dy) * 34 + (tw + dx)];
                    const float p1 = patch[ci * 612 + (th + dy) * 34 + (tw + 16 + dx)];
                    const float4 wa = *(const float4*)&Ws[(ci * 9 + dy * 3 + dx) * 8 + 0];
                    const float4 wb = *(const float4*)&Ws[(ci * 9 + dy * 3 + dx) * 8 + 4];
                    acc[0]  += wa.x * p0; acc[1]  += wa.x * p1;
                    acc[2]  += wa.y * p0; acc[3]  += wa.y * p1;
                    acc[4]  += wa.z * p0; acc[5]  += wa.z * p1;
                    acc[6]  += wa.w * p0; acc[7]  += wa.w * p1;
                    acc[8]  += wb.x * p0; acc[9]  += wb.x * p1;
                    acc[10] += wb.y * p0; acc[11] += wb.y * p1;
                    acc[12] += wb.z * p0; acc[13] += wb.z * p1;
                    acc[14] += wb.w * p0; acc[15] += wb.w * p1;
                }
            }
        }
    }
#pragma unroll
    for (int i = 0; i < 8; i++) {
        const int co = co0 + i;
        const float b = bo[co];
        const size_t o0 = ((size_t)(bt * COUT + co) * HH + (h0 + th)) * WW + (w0 + tw);
        const float c0 = img[(co * HH + h0 + th) * WW + w0 + tw];
        const float c1 = img[(co * HH + h0 + th) * WW + w0 + tw + 16];
        out[o0]      = acc[i * 2 + 0] + b + c0;
        out[o0 + 16] = acc[i * 2 + 1] + b + c1;
    }
}

// ---------------------------------------------------------------------------
extern "C" void kernel_launch(void* const* d_in, const int* in_sizes, int n_in,
                              void* d_out, int out_size)
{
    (void)in_sizes; (void)n_in; (void)out_size;
    const float* x  = (const float*)d_in[0];
    const float* wq = (const float*)d_in[1];
    const float* bq = (const float*)d_in[2];
    const float* wk = (const float*)d_in[3];
    const float* bk = (const float*)d_in[4];
    const float* wv = (const float*)d_in[5];
    const float* bv = (const float*)d_in[6];
    const float* wo = (const float*)d_in[7];
    const float* bo = (const float*)d_in[8];
    float* out = (float*)d_out;

    qkv_conv_kernel<<<dim3(256, 3), 512>>>(x, wq, bq, wk, bk, wv, bv);
    qk_kernel<<<dim3(8, 8, 64), 256>>>();
    softmax_kernel<<<16384, 256>>>();
    pv_kernel<<<dim3(4, 8, 64), 256>>>();
    oconv_kernel<<<dim3(8, 16, 64), 256>>>(wo, bo, out);
}

// round 9
// speedup vs baseline: 1.4632x; 1.0497x over previous
#include <cuda_runtime.h>
#include <math.h>

// Problem constants
#define CIN    64
#define HH     256
#define WW     256
#define COUT   64
#define NHD    8
#define HG     32
#define WG     32
#define NQ     1024
#define DDIM   512
#define NBT    8
#define NHEADS 64
#define KCONV  576
#define ATT_SCALE 0.044194173824159216f  // 1/sqrt(512)

// Scratch (device globals). g_Q is reused as the attention-output image buffer
// after qk_kernel (both are exactly 33.5M floats).
__device__ float g_Q[NHEADS * NQ * DDIM];
__device__ float g_K[NHEADS * NQ * DDIM];
__device__ float g_V[NHEADS * NQ * DDIM];
__device__ float g_S[NHEADS * NQ * NQ];

// FMA lattice macro: consume fragments directly (no am[]/bn[] copy arrays).
#define MMA_ROW(i, AV)                                                        \
    acc[i][0] += (AV) * bv0.x; acc[i][1] += (AV) * bv0.y;                     \
    acc[i][2] += (AV) * bv0.z; acc[i][3] += (AV) * bv0.w;                     \
    acc[i][4] += (AV) * bv1.x; acc[i][5] += (AV) * bv1.y;                     \
    acc[i][6] += (AV) * bv1.z; acc[i][7] += (AV) * bv1.w;

#define MMA_8x8()                                                             \
    MMA_ROW(0, av0.x) MMA_ROW(1, av0.y) MMA_ROW(2, av0.z) MMA_ROW(3, av0.w)  \
    MMA_ROW(4, av1.x) MMA_ROW(5, av1.y) MMA_ROW(6, av1.z) MMA_ROW(7, av1.w)

// ---------------------------------------------------------------------------
// Kernel 1: fused QKV grid-conv.
// Block = 512 threads = 4 samples x (8 co-groups x 16 pos-threads).
// Thread: 4 consecutive positions x 8 output channels (32 acc).
// ---------------------------------------------------------------------------
__global__ __launch_bounds__(512) void qkv_conv_kernel(
    const float* __restrict__ x,
    const float* __restrict__ wq, const float* __restrict__ bq,
    const float* __restrict__ wk, const float* __restrict__ bk,
    const float* __restrict__ wv, const float* __restrict__ bv)
{
    __shared__ float Wc[72 * 68];         // [kl = cil*9+dd][co], pad 68
    __shared__ float pat[4][8][100];      // [s][cil][10x10], halo stays zero

    const int conv = blockIdx.y;
    const float* wsrc = (conv == 0) ? wq : (conv == 1) ? wk : wv;
    const float* bsrc = (conv == 0) ? bq : (conv == 1) ? bk : bv;
    float* dst = (conv == 0) ? g_Q : (conv == 1) ? g_K : g_V;

    const int tid = threadIdx.x;
    const int s   = tid >> 7;          // sample in group 0..3
    const int t2  = tid & 127;
    const int cog = t2 >> 4;           // 0..7 (co0 = cog*8)
    const int pt  = t2 & 15;           // position quad: p = 4*pt + u
    const int gi  = pt >> 1;
    const int gjb = (pt & 1) * 4;
    const int co0 = cog * 8;

    float bias[8];
#pragma unroll
    for (int i = 0; i < 8; i++) bias[i] = bsrc[co0 + i];

    // zero patch buffers once (halo cells are never rewritten)
    for (int i = tid; i < 4 * 8 * 100; i += 512) ((float*)pat)[i] = 0.f;

    for (int g = 0; g < 8; g++) {
        const int qbase = blockIdx.x * 32 + g * 4;   // 4-aligned => same hi
        const int sg = qbase + s;
        const int bt = sg >> 10;
        const int q  = sg & 1023;

        float acc[8][4];
#pragma unroll
        for (int i = 0; i < 8; i++)
#pragma unroll
            for (int u = 0; u < 4; u++) acc[i][u] = bias[i];

        for (int cc = 0; cc < 8; cc++) {
            __syncthreads();   // prev compute (or zero fill) done
            // stage weight chunk: Wc[kl][co] = w[co][cc*8+cil][dy][dx]
            for (int i = tid; i < 4608; i += 512) {
                const int co_s = i / 72;
                const int kl   = i - co_s * 72;
                Wc[kl * 68 + co_s] = wsrc[co_s * KCONV + cc * 72 + kl];
            }
            // stage patch interiors: i = ((cil*8+pgi)*8+pgj)*4 + ss
            for (int i = tid; i < 2048; i += 512) {
                const int ss  = i & 3;
                int r = i >> 2;
                const int pgj = r & 7; r >>= 3;
                const int pgi = r & 7;
                const int cil = r >> 3;
                const int sg2 = qbase + ss;
                const int bt2 = sg2 >> 10;
                const int q2  = sg2 & 1023;
                const int hi2 = q2 >> 5, wi2 = q2 & 31;
                pat[ss][cil][(pgi + 1) * 10 + pgj + 1] =
                    x[((bt2 * CIN + cc * 8 + cil) * HH + (pgi * HG + hi2)) * WW + pgj * WG + wi2];
            }
            __syncthreads();
#pragma unroll
            for (int dy = 0; dy < 3; dy++) {
#pragma unroll
                for (int dx = 0; dx < 3; dx++) {
#pragma unroll
                    for (int cl = 0; cl < 8; cl++) {
                        const float* prow = &pat[s][cl][(gi + dy) * 10 + gjb + dx];
                        const float p0 = prow[0], p1 = prow[1], p2 = prow[2], p3 = prow[3];
                        const float* wrow = &Wc[(cl * 9 + dy * 3 + dx) * 68 + co0];
                        const float4 w0 = *(const float4*)&wrow[0];
                        const float4 w1 = *(const float4*)&wrow[4];
                        acc[0][0] += w0.x * p0; acc[0][1] += w0.x * p1; acc[0][2] += w0.x * p2; acc[0][3] += w0.x * p3;
                        acc[1][0] += w0.y * p0; acc[1][1] += w0.y * p1; acc[1][2] += w0.y * p2; acc[1][3] += w0.y * p3;
                        acc[2][0] += w0.z * p0; acc[2][1] += w0.z * p1; acc[2][2] += w0.z * p2; acc[2][3] += w0.z * p3;
                        acc[3][0] += w0.w * p0; acc[3][1] += w0.w * p1; acc[3][2] += w0.w * p2; acc[3][3] += w0.w * p3;
                        acc[4][0] += w1.x * p0; acc[4][1] += w1.x * p1; acc[4][2] += w1.x * p2; acc[4][3] += w1.x * p3;
                        acc[5][0] += w1.y * p0; acc[5][1] += w1.y * p1; acc[5][2] += w1.y * p2; acc[5][3] += w1.y * p3;
                        acc[6][0] += w1.z * p0; acc[6][1] += w1.z * p1; acc[6][2] += w1.z * p2; acc[6][3] += w1.z * p3;
                        acc[7][0] += w1.w * p0; acc[7][1] += w1.w * p1; acc[7][2] += w1.w * p2; acc[7][3] += w1.w * p3;
                    }
                }
            }
        }
        // write: co = co0+i -> head n=cog, cl=i; d = cl*64 + (4*pt+u)
        float* drow = &dst[((size_t)(bt * NHD + cog) * NQ + q) * DDIM + pt * 4];
#pragma unroll
        for (int i = 0; i < 8; i++) {
            float4 v = make_float4(acc[i][0], acc[i][1], acc[i][2], acc[i][3]);
            *(float4*)&drow[i * 64] = v;
        }
    }
}

// ---------------------------------------------------------------------------
// Kernel 2: S = scale * Q @ K^T. 128x128 tile, BK=16, 256 thr, 8x8 microtile.
// __launch_bounds__(256,2): force <=128 regs so 2 CTAs/SM (occupancy 25%).
// ---------------------------------------------------------------------------
__global__ __launch_bounds__(256, 2) void qk_kernel()
{
    __shared__ float As[16][132];
    __shared__ float Bs[16][132];
    const int h  = blockIdx.z;
    const int m0 = blockIdx.y * 128;
    const int n0 = blockIdx.x * 128;
    const float* A = g_Q + (size_t)h * NQ * DDIM;
    const float* B = g_K + (size_t)h * NQ * DDIM;
    float* C = g_S + (size_t)h * NQ * NQ;

    const int tid = threadIdx.x;
    const int lr = tid >> 2;             // 0..63
    const int lc = (tid & 3) * 4;        // 0,4,8,12
    const int tx = tid & 15, ty = tid >> 4;

    float acc[8][8];
#pragma unroll
    for (int i = 0; i < 8; i++)
#pragma unroll
        for (int j = 0; j < 8; j++) acc[i][j] = 0.f;

    for (int kc = 0; kc < DDIM; kc += 16) {
        const float4 a0 = *(const float4*)&A[(size_t)(m0 + lr) * DDIM + kc + lc];
        const float4 a1 = *(const float4*)&A[(size_t)(m0 + lr + 64) * DDIM + kc + lc];
        const float4 b0 = *(const float4*)&B[(size_t)(n0 + lr) * DDIM + kc + lc];
        const float4 b1 = *(const float4*)&B[(size_t)(n0 + lr + 64) * DDIM + kc + lc];
        __syncthreads();
        As[lc + 0][lr] = a0.x; As[lc + 1][lr] = a0.y; As[lc + 2][lr] = a0.z; As[lc + 3][lr] = a0.w;
        As[lc + 0][lr + 64] = a1.x; As[lc + 1][lr + 64] = a1.y; As[lc + 2][lr + 64] = a1.z; As[lc + 3][lr + 64] = a1.w;
        Bs[lc + 0][lr] = b0.x; Bs[lc + 1][lr] = b0.y; Bs[lc + 2][lr] = b0.z; Bs[lc + 3][lr] = b0.w;
        Bs[lc + 0][lr + 64] = b1.x; Bs[lc + 1][lr + 64] = b1.y; Bs[lc + 2][lr + 64] = b1.z; Bs[lc + 3][lr + 64] = b1.w;
        __syncthreads();
#pragma unroll
        for (int kk = 0; kk < 16; kk++) {
            const float4 av0 = *(const float4*)&As[kk][ty * 4];
            const float4 av1 = *(const float4*)&As[kk][ty * 4 + 64];
            const float4 bv0 = *(const float4*)&Bs[kk][tx * 4];
            const float4 bv1 = *(const float4*)&Bs[kk][tx * 4 + 64];
            MMA_8x8()
        }
    }
#pragma unroll
    for (int i = 0; i < 8; i++) {
        const int m = m0 + ((i < 4) ? (ty * 4 + i) : (64 + ty * 4 + i - 4));
        float4 v0 = make_float4(acc[i][0] * ATT_SCALE, acc[i][1] * ATT_SCALE,
                                acc[i][2] * ATT_SCALE, acc[i][3] * ATT_SCALE);
        float4 v1 = make_float4(acc[i][4] * ATT_SCALE, acc[i][5] * ATT_SCALE,
                                acc[i][6] * ATT_SCALE, acc[i][7] * ATT_SCALE);
        *(float4*)&C[(size_t)m * NQ + n0 + tx * 4] = v0;
        *(float4*)&C[(size_t)m * NQ + n0 + 64 + tx * 4] = v1;
    }
}

// ---------------------------------------------------------------------------
// Kernel 3: row softmax over g_S, in place. One block per 4 rows.
// ---------------------------------------------------------------------------
__global__ __launch_bounds__(256) void softmax_kernel()
{
    __shared__ float redm[8];
    __shared__ float reds[8];
    const int tid = threadIdx.x;
    for (int r = 0; r < 4; r++) {
        float* S = g_S + (size_t)(blockIdx.x * 4 + r) * NQ;
        float v0 = S[tid], v1 = S[tid + 256], v2 = S[tid + 512], v3 = S[tid + 768];
        float m = fmaxf(fmaxf(v0, v1), fmaxf(v2, v3));
#pragma unroll
        for (int o = 16; o > 0; o >>= 1) m = fmaxf(m, __shfl_xor_sync(0xffffffffu, m, o));
        if ((tid & 31) == 0) redm[tid >> 5] = m;
        __syncthreads();
        m = redm[0];
#pragma unroll
        for (int i = 1; i < 8; i++) m = fmaxf(m, redm[i]);
        v0 = __expf(v0 - m); v1 = __expf(v1 - m); v2 = __expf(v2 - m); v3 = __expf(v3 - m);
        float sum = v0 + v1 + v2 + v3;
#pragma unroll
        for (int o = 16; o > 0; o >>= 1) sum += __shfl_xor_sync(0xffffffffu, sum, o);
        if ((tid & 31) == 0) reds[tid >> 5] = sum;
        __syncthreads();
        sum = 0.f;
#pragma unroll
        for (int i = 0; i < 8; i++) sum += reds[i];
        const float inv = 1.0f / sum;
        S[tid] = v0 * inv; S[tid + 256] = v1 * inv; S[tid + 512] = v2 * inv; S[tid + 768] = v3 * inv;
        __syncthreads();
    }
}

// ---------------------------------------------------------------------------
// Kernel 4: Y = P @ V. 128x128 tile, BK=16, 256 thr, 8x8 microtile.
// __launch_bounds__(256,2) for 2 CTAs/SM. Epilogue fuses grid2im scatter.
// ---------------------------------------------------------------------------
__global__ __launch_bounds__(256, 2) void pv_kernel()
{
    __shared__ float As[16][132];
    __shared__ float Bs[16][132];
    const int h  = blockIdx.z;
    const int m0 = blockIdx.y * 128;
    const int n0 = blockIdx.x * 128;
    const float* A = g_S + (size_t)h * NQ * NQ;
    const float* B = g_V + (size_t)h * NQ * DDIM;
    float* img = g_Q;   // g_Q dead after qk_kernel

    const int tid = threadIdx.x;
    const int lr = tid >> 2;
    const int lc = (tid & 3) * 4;
    const int br = tid >> 5;             // 0..7
    const int bc = (tid & 31) * 4;       // 0..124
    const int tx = tid & 15, ty = tid >> 4;

    float acc[8][8];
#pragma unroll
    for (int i = 0; i < 8; i++)
#pragma unroll
        for (int j = 0; j < 8; j++) acc[i][j] = 0.f;

    for (int kc = 0; kc < NQ; kc += 16) {
        const float4 a0 = *(const float4*)&A[(size_t)(m0 + lr) * NQ + kc + lc];
        const float4 a1 = *(const float4*)&A[(size_t)(m0 + lr + 64) * NQ + kc + lc];
        const float4 bA = *(const float4*)&B[(size_t)(kc + br) * DDIM + n0 + bc];
        const float4 bB = *(const float4*)&B[(size_t)(kc + br + 8) * DDIM + n0 + bc];
        __syncthreads();
        As[lc + 0][lr] = a0.x; As[lc + 1][lr] = a0.y; As[lc + 2][lr] = a0.z; As[lc + 3][lr] = a0.w;
        As[lc + 0][lr + 64] = a1.x; As[lc + 1][lr + 64] = a1.y; As[lc + 2][lr + 64] = a1.z; As[lc + 3][lr + 64] = a1.w;
        *(float4*)&Bs[br][bc] = bA;
        *(float4*)&Bs[br + 8][bc] = bB;
        __syncthreads();
#pragma unroll
        for (int kk = 0; kk < 16; kk++) {
            const float4 av0 = *(const float4*)&As[kk][ty * 4];
            const float4 av1 = *(const float4*)&As[kk][ty * 4 + 64];
            const float4 bv0 = *(const float4*)&Bs[kk][tx * 4];
            const float4 bv1 = *(const float4*)&Bs[kk][tx * 4 + 64];
            MMA_8x8()
        }
    }
    // grid2im scatter
    const int bt = h >> 3, nh = h & 7;
#pragma unroll
    for (int i = 0; i < 8; i++) {
        const int q  = m0 + ((i < 4) ? (ty * 4 + i) : (64 + ty * 4 + i - 4));
        const int hi = q >> 5, wi = q & 31;
#pragma unroll
        for (int j = 0; j < 8; j++) {
            const int d = n0 + ((j < 4) ? (tx * 4 + j) : (64 + tx * 4 + j - 4));
            const int cl = d >> 6, r = d & 63;
            const int pgi = r >> 3, pgj = r & 7;
            const int co = nh * 8 + cl;
            img[((bt * COUT + co) * HH + (pgi * HG + hi)) * WW + (pgj * WG + wi)] = acc[i][j];
        }
    }
}

// ---------------------------------------------------------------------------
// Kernel 5: out = img + conv3x3(img, wo) + bo
// ---------------------------------------------------------------------------
__global__ __launch_bounds__(256) void oconv_kernel(
    const float* __restrict__ wo, const float* __restrict__ bo,
    float* __restrict__ out)
{
    __shared__ float patch[8 * 18 * 34];
    __shared__ float Ws[72 * 8];

    const int bz  = blockIdx.z;
    const int bt  = bz >> 3;
    const int co0 = (bz & 7) * 8;
    const int h0  = blockIdx.y * 16;
    const int w0  = blockIdx.x * 32;

    const int tid = threadIdx.x;
    const int th  = tid >> 4;
    const int tw  = tid & 15;

    float acc[16];
#pragma unroll
    for (int i = 0; i < 16; i++) acc[i] = 0.f;

    const float* img = g_Q + (size_t)bt * COUT * HH * WW;

    for (int cc = 0; cc < 8; cc++) {
        const int ci0 = cc * 8;
        __syncthreads();
        for (int i = tid; i < 8 * 18 * 34; i += 256) {
            const int ci = i / 612;
            const int rem = i - ci * 612;
            const int r = rem / 34;
            const int c = rem - r * 34;
            const int gh = h0 - 1 + r, gw = w0 - 1 + c;
            float v = 0.f;
            if (gh >= 0 && gh < HH && gw >= 0 && gw < WW)
                v = img[((ci0 + ci) * HH + gh) * WW + gw];
            patch[i] = v;
        }
        for (int i = tid; i < 576; i += 256) {
            const int co = i / 72;
            const int rem = i - co * 72;
            Ws[rem * 8 + co] = wo[(co0 + co) * KCONV + ci0 * 9 + rem];
        }
        __syncthreads();
#pragma unroll
        for (int dy = 0; dy < 3; dy++) {
#pragma unroll
            for (int dx = 0; dx < 3; dx++) {
#pragma unroll
                for (int ci = 0; ci < 8; ci++) {
                    const float p0 = patch[ci * 612 + (th + dy) * 34 + (tw + dx)];
                    const float p1 = patch[ci * 612 + (th + dy) * 34 + (tw + 16 + dx)];
                    const float4 wa = *(const float4*)&Ws[(ci * 9 + dy * 3 + dx) * 8 + 0];
                    const float4 wb = *(const float4*)&Ws[(ci * 9 + dy * 3 + dx) * 8 + 4];
                    acc[0]  += wa.x * p0; acc[1]  += wa.x * p1;
                    acc[2]  += wa.y * p0; acc[3]  += wa.y * p1;
                    acc[4]  += wa.z * p0; acc[5]  += wa.z * p1;
                    acc[6]  += wa.w * p0; acc[7]  += wa.w * p1;
                    acc[8]  += wb.x * p0; acc[9]  += wb.x * p1;
                    acc[10] += wb.y * p0; acc[11] += wb.y * p1;
                    acc[12] += wb.z * p0; acc[13] += wb.z * p1;
                    acc[14] += wb.w * p0; acc[15] += wb.w * p1;
                }
            }
        }
    }
#pragma unroll
    for (int i = 0; i < 8; i++) {
        const int co = co0 + i;
        const float b = bo[co];
        const size_t o0 = ((size_t)(bt * COUT + co) * HH + (h0 + th)) * WW + (w0 + tw);
        const float c0 = img[(co * HH + h0 + th) * WW + w0 + tw];
        const float c1 = img[(co * HH + h0 + th) * WW + w0 + tw + 16];
        out[o0]      = acc[i * 2 + 0] + b + c0;
        out[o0 + 16] = acc[i * 2 + 1] + b + c1;
    }
}

// ---------------------------------------------------------------------------
extern "C" void kernel_launch(void* const* d_in, const int* in_sizes, int n_in,
                              void* d_out, int out_size)
{
    (void)in_sizes; (void)n_in; (void)out_size;
    const float* x  = (const float*)d_in[0];
    const float* wq = (const float*)d_in[1];
    const float* bq = (const float*)d_in[2];
    const float* wk = (const float*)d_in[3];
    const float* bk = (const float*)d_in[4];
    const float* wv = (const float*)d_in[5];
    const float* bv = (const float*)d_in[6];
    const float* wo = (const float*)d_in[7];
    const float* bo = (const float*)d_in[8];
    float* out = (float*)d_out;

    qkv_conv_kernel<<<dim3(256, 3), 512>>>(x, wq, bq, wk, bk, wv, bv);
    qk_kernel<<<dim3(8, 8, 64), 256>>>();
    softmax_kernel<<<16384, 256>>>();
    pv_kernel<<<dim3(4, 8, 64), 256>>>();
    oconv_kernel<<<dim3(8, 16, 64), 256>>>(wo, bo, out);
}

// round 10
// speedup vs baseline: 1.5766x; 1.0775x over previous
#include <cuda_runtime.h>
#include <math.h>

// Problem constants
#define CIN    64
#define HH     256
#define WW     256
#define COUT   64
#define NHD    8
#define HG     32
#define WG     32
#define NQ     1024
#define DDIM   512
#define NBT    8
#define NHEADS 64
#define KCONV  576
#define ATT_SCALE 0.044194173824159216f  // 1/sqrt(512)

typedef unsigned long long u64;

// Packed fp32x2 FMA (Blackwell): d = a*b + d elementwise on {lo,hi} pairs.
// ptxas never emits FFMA2 from C++; PTX fma.rn.f32x2 is the only route.
#define FMA2(d, a, b) \
    asm("fma.rn.f32x2 %0, %1, %2, %0;" : "+l"(d) : "l"(a), "l"(b))
// Duplicate one fp32 into both lanes of a 64-bit pair.
#define DUP2(d, s) \
    asm("mov.b64 %0, {%1, %1};" : "=l"(d) : "r"(__float_as_uint(s)))
// Pack two fp32 into a pair {lo, hi}.
#define PK2(d, lo, hi) \
    asm("mov.b64 %0, {%1, %2};" : "=l"(d) : "r"(__float_as_uint(lo)), "r"(__float_as_uint(hi)))
// Unpack a pair.
#define UNPK(lo, hi, v) \
    { unsigned _l, _h; asm("mov.b64 {%0, %1}, %2;" : "=r"(_l), "=r"(_h) : "l"(v)); \
      lo = __uint_as_float(_l); hi = __uint_as_float(_h); }

// Scratch (device globals). g_Q is reused as the attention-output image buffer
// after qk_kernel (both are exactly 33.5M floats).
__device__ float g_Q[NHEADS * NQ * DDIM];
__device__ float g_K[NHEADS * NQ * DDIM];
__device__ float g_V[NHEADS * NQ * DDIM];
__device__ float g_S[NHEADS * NQ * NQ];

// GEMM row macro: acc2[i][0..3] are {j,j+1} pairs; bp0/bp1 are B-pairs.
#define QROW(i, s) { u64 _a; DUP2(_a, s);                                    \
    FMA2(acc2[i][0], _a, bp0.x); FMA2(acc2[i][1], _a, bp0.y);                \
    FMA2(acc2[i][2], _a, bp1.x); FMA2(acc2[i][3], _a, bp1.y); }

#define QMMA()                                                                \
    QROW(0, av0.x) QROW(1, av0.y) QROW(2, av0.z) QROW(3, av0.w)              \
    QROW(4, av1.x) QROW(5, av1.y) QROW(6, av1.z) QROW(7, av1.w)

// ---------------------------------------------------------------------------
// Kernel 1: fused QKV grid-conv.
// Block = 512 threads = 4 samples x (8 co-groups x 16 pos-threads).
// Thread: 4 consecutive positions x 8 output channels, co packed in pairs.
// ---------------------------------------------------------------------------
__global__ __launch_bounds__(512) void qkv_conv_kernel(
    const float* __restrict__ x,
    const float* __restrict__ wq, const float* __restrict__ bq,
    const float* __restrict__ wk, const float* __restrict__ bk,
    const float* __restrict__ wv, const float* __restrict__ bv)
{
    __shared__ float Wc[72 * 68];         // [kl = cil*9+dd][co], pad 68
    __shared__ float pat[4][8][100];      // [s][cil][10x10], halo stays zero

    const int conv = blockIdx.y;
    const float* wsrc = (conv == 0) ? wq : (conv == 1) ? wk : wv;
    const float* bsrc = (conv == 0) ? bq : (conv == 1) ? bk : bv;
    float* dst = (conv == 0) ? g_Q : (conv == 1) ? g_K : g_V;

    const int tid = threadIdx.x;
    const int s   = tid >> 7;          // sample in group 0..3
    const int t2  = tid & 127;
    const int cog = t2 >> 4;           // 0..7 (co0 = cog*8)
    const int pt  = t2 & 15;           // position quad: p = 4*pt + u
    const int gi  = pt >> 1;
    const int gjb = (pt & 1) * 4;
    const int co0 = cog * 8;

    u64 bias2[4];                      // co pairs {co0+2c, co0+2c+1}
#pragma unroll
    for (int c = 0; c < 4; c++) PK2(bias2[c], bsrc[co0 + 2 * c], bsrc[co0 + 2 * c + 1]);

    // zero patch buffers once (halo cells are never rewritten)
    for (int i = tid; i < 4 * 8 * 100; i += 512) ((float*)pat)[i] = 0.f;

    for (int g = 0; g < 8; g++) {
        const int qbase = blockIdx.x * 32 + g * 4;   // 4-aligned => same hi
        const int sg = qbase + s;
        const int bt = sg >> 10;
        const int q  = sg & 1023;

        u64 acc2[4][4];                // [co-pair][pos]
#pragma unroll
        for (int c = 0; c < 4; c++)
#pragma unroll
            for (int u = 0; u < 4; u++) acc2[c][u] = bias2[c];

        for (int cc = 0; cc < 8; cc++) {
            __syncthreads();   // prev compute (or zero fill) done
            // stage weight chunk: Wc[kl][co] = w[co][cc*8+cil][dy][dx]
            for (int i = tid; i < 4608; i += 512) {
                const int co_s = i / 72;
                const int kl   = i - co_s * 72;
                Wc[kl * 68 + co_s] = wsrc[co_s * KCONV + cc * 72 + kl];
            }
            // stage patch interiors: i = ((cil*8+pgi)*8+pgj)*4 + ss
            for (int i = tid; i < 2048; i += 512) {
                const int ss  = i & 3;
                int r = i >> 2;
                const int pgj = r & 7; r >>= 3;
                const int pgi = r & 7;
                const int cil = r >> 3;
                const int sg2 = qbase + ss;
                const int bt2 = sg2 >> 10;
                const int q2  = sg2 & 1023;
                const int hi2 = q2 >> 5, wi2 = q2 & 31;
                pat[ss][cil][(pgi + 1) * 10 + pgj + 1] =
                    x[((bt2 * CIN + cc * 8 + cil) * HH + (pgi * HG + hi2)) * WW + pgj * WG + wi2];
            }
            __syncthreads();
#pragma unroll
            for (int dy = 0; dy < 3; dy++) {
#pragma unroll
                for (int dx = 0; dx < 3; dx++) {
#pragma unroll
                    for (int cl = 0; cl < 8; cl++) {
                        const float* prow = &pat[s][cl][(gi + dy) * 10 + gjb + dx];
                        const float p0 = prow[0], p1 = prow[1], p2 = prow[2], p3 = prow[3];
                        const float* wrow = &Wc[(cl * 9 + dy * 3 + dx) * 68 + co0];
                        const ulonglong2 wA = *(const ulonglong2*)&wrow[0];  // {w0,w1},{w2,w3}
                        const ulonglong2 wB = *(const ulonglong2*)&wrow[4];  // {w4,w5},{w6,w7}
                        u64 pd;
                        DUP2(pd, p0);
                        FMA2(acc2[0][0], wA.x, pd); FMA2(acc2[1][0], wA.y, pd);
                        FMA2(acc2[2][0], wB.x, pd); FMA2(acc2[3][0], wB.y, pd);
                        DUP2(pd, p1);
                        FMA2(acc2[0][1], wA.x, pd); FMA2(acc2[1][1], wA.y, pd);
                        FMA2(acc2[2][1], wB.x, pd); FMA2(acc2[3][1], wB.y, pd);
                        DUP2(pd, p2);
                        FMA2(acc2[0][2], wA.x, pd); FMA2(acc2[1][2], wA.y, pd);
                        FMA2(acc2[2][2], wB.x, pd); FMA2(acc2[3][2], wB.y, pd);
                        DUP2(pd, p3);
                        FMA2(acc2[0][3], wA.x, pd); FMA2(acc2[1][3], wA.y, pd);
                        FMA2(acc2[2][3], wB.x, pd); FMA2(acc2[3][3], wB.y, pd);
                    }
                }
            }
        }
        // unpack then write: co = co0+i -> head n=cog, cl=i; d = cl*64 + (4*pt+u)
        float accf[8][4];
#pragma unroll
        for (int c = 0; c < 4; c++)
#pragma unroll
            for (int u = 0; u < 4; u++) { UNPK(accf[2 * c][u], accf[2 * c + 1][u], acc2[c][u]); }
        float* drow = &dst[((size_t)(bt * NHD + cog) * NQ + q) * DDIM + pt * 4];
#pragma unroll
        for (int i = 0; i < 8; i++) {
            float4 v = make_float4(accf[i][0], accf[i][1], accf[i][2], accf[i][3]);
            *(float4*)&drow[i * 64] = v;
        }
    }
}

// ---------------------------------------------------------------------------
// Kernel 2: S = scale * Q @ K^T. 128x128 tile, BK=16, 256 thr, 8x8 microtile
// with j-packed f32x2 accumulators. __launch_bounds__(256,2) for 2 CTAs/SM.
// ---------------------------------------------------------------------------
__global__ __launch_bounds__(256, 2) void qk_kernel()
{
    __shared__ float As[16][132];
    __shared__ float Bs[16][132];
    const int h  = blockIdx.z;
    const int m0 = blockIdx.y * 128;
    const int n0 = blockIdx.x * 128;
    const float* A = g_Q + (size_t)h * NQ * DDIM;
    const float* B = g_K + (size_t)h * NQ * DDIM;
    float* C = g_S + (size_t)h * NQ * NQ;

    const int tid = threadIdx.x;
    const int lr = tid >> 2;             // 0..63
    const int lc = (tid & 3) * 4;        // 0,4,8,12
    const int tx = tid & 15, ty = tid >> 4;

    u64 acc2[8][4];                      // [i][j-pair]
#pragma unroll
    for (int i = 0; i < 8; i++)
#pragma unroll
        for (int j = 0; j < 4; j++) acc2[i][j] = 0ull;

    for (int kc = 0; kc < DDIM; kc += 16) {
        const float4 a0 = *(const float4*)&A[(size_t)(m0 + lr) * DDIM + kc + lc];
        const float4 a1 = *(const float4*)&A[(size_t)(m0 + lr + 64) * DDIM + kc + lc];
        const float4 b0 = *(const float4*)&B[(size_t)(n0 + lr) * DDIM + kc + lc];
        const float4 b1 = *(const float4*)&B[(size_t)(n0 + lr + 64) * DDIM + kc + lc];
        __syncthreads();
        As[lc + 0][lr] = a0.x; As[lc + 1][lr] = a0.y; As[lc + 2][lr] = a0.z; As[lc + 3][lr] = a0.w;
        As[lc + 0][lr + 64] = a1.x; As[lc + 1][lr + 64] = a1.y; As[lc + 2][lr + 64] = a1.z; As[lc + 3][lr + 64] = a1.w;
        Bs[lc + 0][lr] = b0.x; Bs[lc + 1][lr] = b0.y; Bs[lc + 2][lr] = b0.z; Bs[lc + 3][lr] = b0.w;
        Bs[lc + 0][lr + 64] = b1.x; Bs[lc + 1][lr + 64] = b1.y; Bs[lc + 2][lr + 64] = b1.z; Bs[lc + 3][lr + 64] = b1.w;
        __syncthreads();
#pragma unroll
        for (int kk = 0; kk < 16; kk++) {
            const float4 av0 = *(const float4*)&As[kk][ty * 4];
            const float4 av1 = *(const float4*)&As[kk][ty * 4 + 64];
            const ulonglong2 bp0 = *(const ulonglong2*)&Bs[kk][tx * 4];       // {b0,b1},{b2,b3}
            const ulonglong2 bp1 = *(const ulonglong2*)&Bs[kk][tx * 4 + 64];  // {b4,b5},{b6,b7}
            QMMA()
        }
    }
#pragma unroll
    for (int i = 0; i < 8; i++) {
        const int m = m0 + ((i < 4) ? (ty * 4 + i) : (64 + ty * 4 + i - 4));
        float f[8];
        UNPK(f[0], f[1], acc2[i][0]); UNPK(f[2], f[3], acc2[i][1]);
        UNPK(f[4], f[5], acc2[i][2]); UNPK(f[6], f[7], acc2[i][3]);
        float4 v0 = make_float4(f[0] * ATT_SCALE, f[1] * ATT_SCALE, f[2] * ATT_SCALE, f[3] * ATT_SCALE);
        float4 v1 = make_float4(f[4] * ATT_SCALE, f[5] * ATT_SCALE, f[6] * ATT_SCALE, f[7] * ATT_SCALE);
        *(float4*)&C[(size_t)m * NQ + n0 + tx * 4] = v0;
        *(float4*)&C[(size_t)m * NQ + n0 + 64 + tx * 4] = v1;
    }
}

// ---------------------------------------------------------------------------
// Kernel 3: row softmax over g_S, in place. One block per 4 rows.
// ---------------------------------------------------------------------------
__global__ __launch_bounds__(256) void softmax_kernel()
{
    __shared__ float redm[8];
    __shared__ float reds[8];
    const int tid = threadIdx.x;
    for (int r = 0; r < 4; r++) {
        float* S = g_S + (size_t)(blockIdx.x * 4 + r) * NQ;
        float v0 = S[tid], v1 = S[tid + 256], v2 = S[tid + 512], v3 = S[tid + 768];
        float m = fmaxf(fmaxf(v0, v1), fmaxf(v2, v3));
#pragma unroll
        for (int o = 16; o > 0; o >>= 1) m = fmaxf(m, __shfl_xor_sync(0xffffffffu, m, o));
        if ((tid & 31) == 0) redm[tid >> 5] = m;
        __syncthreads();
        m = redm[0];
#pragma unroll
        for (int i = 1; i < 8; i++) m = fmaxf(m, redm[i]);
        v0 = __expf(v0 - m); v1 = __expf(v1 - m); v2 = __expf(v2 - m); v3 = __expf(v3 - m);
        float sum = v0 + v1 + v2 + v3;
#pragma unroll
        for (int o = 16; o > 0; o >>= 1) sum += __shfl_xor_sync(0xffffffffu, sum, o);
        if ((tid & 31) == 0) reds[tid >> 5] = sum;
        __syncthreads();
        sum = 0.f;
#pragma unroll
        for (int i = 0; i < 8; i++) sum += reds[i];
        const float inv = 1.0f / sum;
        S[tid] = v0 * inv; S[tid + 256] = v1 * inv; S[tid + 512] = v2 * inv; S[tid + 768] = v3 * inv;
        __syncthreads();
    }
}

// ---------------------------------------------------------------------------
// Kernel 4: Y = P @ V. 128x128 tile, BK=16, 256 thr, f32x2 microtile.
// __launch_bounds__(256,2) for 2 CTAs/SM. Epilogue fuses grid2im scatter.
// ---------------------------------------------------------------------------
__global__ __launch_bounds__(256, 2) void pv_kernel()
{
    __shared__ float As[16][132];
    __shared__ float Bs[16][132];
    const int h  = blockIdx.z;
    const int m0 = blockIdx.y * 128;
    const int n0 = blockIdx.x * 128;
    const float* A = g_S + (size_t)h * NQ * NQ;
    const float* B = g_V + (size_t)h * NQ * DDIM;
    float* img = g_Q;   // g_Q dead after qk_kernel

    const int tid = threadIdx.x;
    const int lr = tid >> 2;
    const int lc = (tid & 3) * 4;
    const int br = tid >> 5;             // 0..7
    const int bc = (tid & 31) * 4;       // 0..124
    const int tx = tid & 15, ty = tid >> 4;

    u64 acc2[8][4];
#pragma unroll
    for (int i = 0; i < 8; i++)
#pragma unroll
        for (int j = 0; j < 4; j++) acc2[i][j] = 0ull;

    for (int kc = 0; kc < NQ; kc += 16) {
        const float4 a0 = *(const float4*)&A[(size_t)(m0 + lr) * NQ + kc + lc];
        const float4 a1 = *(const float4*)&A[(size_t)(m0 + lr + 64) * NQ + kc + lc];
        const float4 bA = *(const float4*)&B[(size_t)(kc + br) * DDIM + n0 + bc];
        const float4 bB = *(const float4*)&B[(size_t)(kc + br + 8) * DDIM + n0 + bc];
        __syncthreads();
        As[lc + 0][lr] = a0.x; As[lc + 1][lr] = a0.y; As[lc + 2][lr] = a0.z; As[lc + 3][lr] = a0.w;
        As[lc + 0][lr + 64] = a1.x; As[lc + 1][lr + 64] = a1.y; As[lc + 2][lr + 64] = a1.z; As[lc + 3][lr + 64] = a1.w;
        *(float4*)&Bs[br][bc] = bA;
        *(float4*)&Bs[br + 8][bc] = bB;
        __syncthreads();
#pragma unroll
        for (int kk = 0; kk < 16; kk++) {
            const float4 av0 = *(const float4*)&As[kk][ty * 4];
            const float4 av1 = *(const float4*)&As[kk][ty * 4 + 64];
            const ulonglong2 bp0 = *(const ulonglong2*)&Bs[kk][tx * 4];
            const ulonglong2 bp1 = *(const ulonglong2*)&Bs[kk][tx * 4 + 64];
            QMMA()
        }
    }
    // grid2im scatter
    const int bt = h >> 3, nh = h & 7;
#pragma unroll
    for (int i = 0; i < 8; i++) {
        const int q  = m0 + ((i < 4) ? (ty * 4 + i) : (64 + ty * 4 + i - 4));
        const int hi = q >> 5, wi = q & 31;
        float f[8];
        UNPK(f[0], f[1], acc2[i][0]); UNPK(f[2], f[3], acc2[i][1]);
        UNPK(f[4], f[5], acc2[i][2]); UNPK(f[6], f[7], acc2[i][3]);
#pragma unroll
        for (int j = 0; j < 8; j++) {
            const int d = n0 + ((j < 4) ? (tx * 4 + j) : (64 + tx * 4 + j - 4));
            const int cl = d >> 6, r = d & 63;
            const int pgi = r >> 3, pgj = r & 7;
            const int co = nh * 8 + cl;
            img[((bt * COUT + co) * HH + (pgi * HG + hi)) * WW + (pgj * WG + wi)] = f[j];
        }
    }
}

// ---------------------------------------------------------------------------
// Kernel 5: out = img + conv3x3(img, wo) + bo ; co packed in f32x2 pairs.
// ---------------------------------------------------------------------------
__global__ __launch_bounds__(256) void oconv_kernel(
    const float* __restrict__ wo, const float* __restrict__ bo,
    float* __restrict__ out)
{
    __shared__ float patch[8 * 18 * 34];
    __shared__ float Ws[72 * 8];

    const int bz  = blockIdx.z;
    const int bt  = bz >> 3;
    const int co0 = (bz & 7) * 8;
    const int h0  = blockIdx.y * 16;
    const int w0  = blockIdx.x * 32;

    const int tid = threadIdx.x;
    const int th  = tid >> 4;
    const int tw  = tid & 15;

    u64 acc2[4][2];                     // [co-pair][pos: tw, tw+16]
#pragma unroll
    for (int c = 0; c < 4; c++) { acc2[c][0] = 0ull; acc2[c][1] = 0ull; }

    const float* img = g_Q + (size_t)bt * COUT * HH * WW;

    for (int cc = 0; cc < 8; cc++) {
        const int ci0 = cc * 8;
        __syncthreads();
        for (int i = tid; i < 8 * 18 * 34; i += 256) {
            const int ci = i / 612;
            const int rem = i - ci * 612;
            const int r = rem / 34;
            const int c = rem - r * 34;
            const int gh = h0 - 1 + r, gw = w0 - 1 + c;
            float v = 0.f;
            if (gh >= 0 && gh < HH && gw >= 0 && gw < WW)
                v = img[((ci0 + ci) * HH + gh) * WW + gw];
            patch[i] = v;
        }
        for (int i = tid; i < 576; i += 256) {
            const int co = i / 72;
            const int rem = i - co * 72;
            Ws[rem * 8 + co] = wo[(co0 + co) * KCONV + ci0 * 9 + rem];
        }
        __syncthreads();
#pragma unroll
        for (int dy = 0; dy < 3; dy++) {
#pragma unroll
            for (int dx = 0; dx < 3; dx++) {
#pragma unroll
                for (int ci = 0; ci < 8; ci++) {
                    const float p0 = patch[ci * 612 + (th + dy) * 34 + (tw + dx)];
                    const float p1 = patch[ci * 612 + (th + dy) * 34 + (tw + 16 + dx)];
                    const float* wrow = &Ws[(ci * 9 + dy * 3 + dx) * 8];
                    const ulonglong2 wA = *(const ulonglong2*)&wrow[0];  // {w0,w1},{w2,w3}
                    const ulonglong2 wB = *(const ulonglong2*)&wrow[4];  // {w4,w5},{w6,w7}
                    u64 pd0, pd1;
                    DUP2(pd0, p0); DUP2(pd1, p1);
                    FMA2(acc2[0][0], wA.x, pd0); FMA2(acc2[1][0], wA.y, pd0);
                    FMA2(acc2[2][0], wB.x, pd0); FMA2(acc2[3][0], wB.y, pd0);
                    FMA2(acc2[0][1], wA.x, pd1); FMA2(acc2[1][1], wA.y, pd1);
                    FMA2(acc2[2][1], wB.x, pd1); FMA2(acc2[3][1], wB.y, pd1);
                }
            }
        }
    }
#pragma unroll
    for (int c = 0; c < 4; c++) {
        float a00, a10, a01, a11;
        UNPK(a00, a10, acc2[c][0]);   // co0+2c, co0+2c+1 at pos tw
        UNPK(a01, a11, acc2[c][1]);   // at pos tw+16
        const int coA = co0 + 2 * c;
        const int coB = coA + 1;
        const float bA = bo[coA], bB = bo[coB];
        const size_t oA = ((size_t)(bt * COUT + coA) * HH + (h0 + th)) * WW + (w0 + tw);
        const size_t oB = ((size_t)(bt * COUT + coB) * HH + (h0 + th)) * WW + (w0 + tw);
        out[oA]      = a00 + bA + img[(coA * HH + h0 + th) * WW + w0 + tw];
        out[oA + 16] = a01 + bA + img[(coA * HH + h0 + th) * WW + w0 + tw + 16];
        out[oB]      = a10 + bB + img[(coB * HH + h0 + th) * WW + w0 + tw];
        out[oB + 16] = a11 + bB + img[(coB * HH + h0 + th) * WW + w0 + tw + 16];
    }
}

// ---------------------------------------------------------------------------
extern "C" void kernel_launch(void* const* d_in, const int* in_sizes, int n_in,
                              void* d_out, int out_size)
{
    (void)in_sizes; (void)n_in; (void)out_size;
    const float* x  = (const float*)d_in[0];
    const float* wq = (const float*)d_in[1];
    const float* bq = (const float*)d_in[2];
    const float* wk = (const float*)d_in[3];
    const float* bk = (const float*)d_in[4];
    const float* wv = (const float*)d_in[5];
    const float* bv = (const float*)d_in[6];
    const float* wo = (const float*)d_in[7];
    const float* bo = (const float*)d_in[8];
    float* out = (float*)d_out;

    qkv_conv_kernel<<<dim3(256, 3), 512>>>(x, wq, bq, wk, bk, wv, bv);
    qk_kernel<<<dim3(8, 8, 64), 256>>>();
    softmax_kernel<<<16384, 256>>>();
    pv_kernel<<<dim3(4, 8, 64), 256>>>();
    oconv_kernel<<<dim3(8, 16, 64), 256>>>(wo, bo, out);
}

// round 11
// speedup vs baseline: 1.8217x; 1.1554x over previous
#include <cuda_runtime.h>
#include <math.h>

// Problem constants
#define CIN    64
#define HH     256
#define WW     256
#define COUT   64
#define NHD    8
#define HG     32
#define WG     32
#define NQ     1024
#define DDIM   512
#define NBT    8
#define NHEADS 64
#define KCONV  576
#define ATT_SCALE 0.044194173824159216f  // 1/sqrt(512)

typedef unsigned long long u64;

// Packed fp32x2 FMA (Blackwell): d = a*b + d elementwise on {lo,hi} pairs.
#define FMA2(d, a, b) \
    asm("fma.rn.f32x2 %0, %1, %2, %0;" : "+l"(d) : "l"(a), "l"(b))
#define DUP2(d, s) \
    asm("mov.b64 %0, {%1, %1};" : "=l"(d) : "r"(__float_as_uint(s)))
#define PK2(d, lo, hi) \
    asm("mov.b64 %0, {%1, %2};" : "=l"(d) : "r"(__float_as_uint(lo)), "r"(__float_as_uint(hi)))
#define UNPK(lo, hi, v) \
    { unsigned _l, _h; asm("mov.b64 {%0, %1}, %2;" : "=r"(_l), "=r"(_h) : "l"(v)); \
      lo = __uint_as_float(_l); hi = __uint_as_float(_h); }

// Scratch (device globals). g_Q is reused as the attention-output image buffer
// after qk_kernel (both are exactly 33.5M floats).
__device__ float g_Q[NHEADS * NQ * DDIM];
__device__ float g_K[NHEADS * NQ * DDIM];
__device__ float g_V[NHEADS * NQ * DDIM];
__device__ float g_S[NHEADS * NQ * NQ];

// GEMM row macro: acc2[i][0..3] are {j,j+1} pairs; bp0/bp1 are B-pairs.
#define QROW(i, s) { u64 _a; DUP2(_a, s);                                    \
    FMA2(acc2[i][0], _a, bp0.x); FMA2(acc2[i][1], _a, bp0.y);                \
    FMA2(acc2[i][2], _a, bp1.x); FMA2(acc2[i][3], _a, bp1.y); }

#define QMMA()                                                                \
    QROW(0, av0.x) QROW(1, av0.y) QROW(2, av0.z) QROW(3, av0.w)              \
    QROW(4, av1.x) QROW(5, av1.y) QROW(6, av1.z) QROW(7, av1.w)

// Conv FMA group: 8 co-pair FMA2s against one duplicated pixel.
#define CFMA(u, P) { u64 _pd; DUP2(_pd, P);                                  \
    FMA2(acc2[0][u], wA.x, _pd); FMA2(acc2[1][u], wA.y, _pd);                \
    FMA2(acc2[2][u], wB.x, _pd); FMA2(acc2[3][u], wB.y, _pd);                \
    FMA2(acc2[4][u], wC.x, _pd); FMA2(acc2[5][u], wC.y, _pd);                \
    FMA2(acc2[6][u], wD.x, _pd); FMA2(acc2[7][u], wD.y, _pd); }

// ---------------------------------------------------------------------------
// Kernel 1: fused QKV grid-conv.
// Block = 512 threads = 8 samples x (4 co-groups x 16 pos-threads).
// Thread: 4 consecutive positions x 16 output channels (8 co-pairs), f32x2.
// Weights/patches staged per ci-chunk, shared by 8 samples.
// ---------------------------------------------------------------------------
__global__ __launch_bounds__(512) void qkv_conv_kernel(
    const float* __restrict__ x,
    const float* __restrict__ wq, const float* __restrict__ bq,
    const float* __restrict__ wk, const float* __restrict__ bk,
    const float* __restrict__ wv, const float* __restrict__ bv)
{
    __shared__ float Wc[72 * 68];         // [kl = cil*9+dd][co], pad 68
    __shared__ float pat[8][8][100];      // [s][cil][10x10], halo stays zero

    const int conv = blockIdx.y;
    const float* wsrc = (conv == 0) ? wq : (conv == 1) ? wk : wv;
    const float* bsrc = (conv == 0) ? bq : (conv == 1) ? bk : bv;
    float* dst = (conv == 0) ? g_Q : (conv == 1) ? g_K : g_V;

    const int tid = threadIdx.x;
    const int s   = tid >> 6;          // sample in group 0..7
    const int t2  = tid & 63;
    const int cog = t2 >> 4;           // 0..3 (co0 = cog*16)
    const int pt  = t2 & 15;           // position quad: p = 4*pt + u
    const int gi  = pt >> 1;
    const int gjb = (pt & 1) * 4;
    const int co0 = cog * 16;

    u64 bias2[8];                      // co pairs {co0+2c, co0+2c+1}
#pragma unroll
    for (int c = 0; c < 8; c++) PK2(bias2[c], bsrc[co0 + 2 * c], bsrc[co0 + 2 * c + 1]);

    // zero patch buffers once (halo cells are never rewritten)
    for (int i = tid; i < 8 * 8 * 100; i += 512) ((float*)pat)[i] = 0.f;

    for (int g = 0; g < 4; g++) {
        const int qbase = blockIdx.x * 32 + g * 8;   // 8-aligned group
        const int sg = qbase + s;
        const int bt = sg >> 10;
        const int q  = sg & 1023;

        u64 acc2[8][4];                // [co-pair][pos]
#pragma unroll
        for (int c = 0; c < 8; c++)
#pragma unroll
            for (int u = 0; u < 4; u++) acc2[c][u] = bias2[c];

        for (int cc = 0; cc < 8; cc++) {
            __syncthreads();   // prev compute (or zero fill) done
            // stage weight chunk: Wc[kl][co] = w[co][cc*8+cil][dy][dx]
            for (int i = tid; i < 4608; i += 512) {
                const int co_s = i / 72;
                const int kl   = i - co_s * 72;
                Wc[kl * 68 + co_s] = wsrc[co_s * KCONV + cc * 72 + kl];
            }
            // stage patch interiors: i = ((cil*8+pgi)*8+pgj)*8 + ss
            for (int i = tid; i < 4096; i += 512) {
                const int ss  = i & 7;
                int r = i >> 3;
                const int pgj = r & 7; r >>= 3;
                const int pgi = r & 7;
                const int cil = r >> 3;
                const int sg2 = qbase + ss;
                const int bt2 = sg2 >> 10;
                const int q2  = sg2 & 1023;
                const int hi2 = q2 >> 5, wi2 = q2 & 31;
                pat[ss][cil][(pgi + 1) * 10 + pgj + 1] =
                    x[((bt2 * CIN + cc * 8 + cil) * HH + (pgi * HG + hi2)) * WW + pgj * WG + wi2];
            }
            __syncthreads();
#pragma unroll
            for (int dy = 0; dy < 3; dy++) {
#pragma unroll
                for (int dx = 0; dx < 3; dx++) {
#pragma unroll
                    for (int cl = 0; cl < 8; cl++) {
                        const float* prow = &pat[s][cl][(gi + dy) * 10 + gjb + dx];
                        const float p0 = prow[0], p1 = prow[1], p2 = prow[2], p3 = prow[3];
                        const float* wrow = &Wc[(cl * 9 + dy * 3 + dx) * 68 + co0];
                        const ulonglong2 wA = *(const ulonglong2*)&wrow[0];
                        const ulonglong2 wB = *(const ulonglong2*)&wrow[4];
                        const ulonglong2 wC = *(const ulonglong2*)&wrow[8];
                        const ulonglong2 wD = *(const ulonglong2*)&wrow[12];
                        CFMA(0, p0) CFMA(1, p1) CFMA(2, p2) CFMA(3, p3)
                    }
                }
            }
        }
        // unpack then write: co = co0+i -> head n=co>>3, cl=co&7; d = cl*64 + (4*pt+u)
        float accf[16][4];
#pragma unroll
        for (int c = 0; c < 8; c++)
#pragma unroll
            for (int u = 0; u < 4; u++) { UNPK(accf[2 * c][u], accf[2 * c + 1][u], acc2[c][u]); }
#pragma unroll
        for (int i = 0; i < 16; i++) {
            const int co = co0 + i;
            const int n = co >> 3, cl = co & 7;
            float4 v = make_float4(accf[i][0], accf[i][1], accf[i][2], accf[i][3]);
            *(float4*)&dst[((size_t)(bt * NHD + n) * NQ + q) * DDIM + cl * 64 + pt * 4] = v;
        }
    }
}

// ---------------------------------------------------------------------------
// Kernel 2: S = scale * Q @ K^T. 128x128 tile, BK=16, 256 thr, f32x2 microtile,
// double-buffered smem (one barrier per chunk). (256,2) for 2 CTAs/SM.
// ---------------------------------------------------------------------------
__global__ __launch_bounds__(256, 2) void qk_kernel()
{
    __shared__ float As[2][16][132];
    __shared__ float Bs[2][16][132];
    const int h  = blockIdx.z;
    const int m0 = blockIdx.y * 128;
    const int n0 = blockIdx.x * 128;
    const float* A = g_Q + (size_t)h * NQ * DDIM;
    const float* B = g_K + (size_t)h * NQ * DDIM;
    float* C = g_S + (size_t)h * NQ * NQ;

    const int tid = threadIdx.x;
    const int lr = tid >> 2;             // 0..63
    const int lc = (tid & 3) * 4;        // 0,4,8,12
    const int tx = tid & 15, ty = tid >> 4;

    u64 acc2[8][4];
#pragma unroll
    for (int i = 0; i < 8; i++)
#pragma unroll
        for (int j = 0; j < 4; j++) acc2[i][j] = 0ull;

    // prologue: stage chunk 0 into buffer 0
    {
        const float4 a0 = *(const float4*)&A[(size_t)(m0 + lr) * DDIM + lc];
        const float4 a1 = *(const float4*)&A[(size_t)(m0 + lr + 64) * DDIM + lc];
        const float4 b0 = *(const float4*)&B[(size_t)(n0 + lr) * DDIM + lc];
        const float4 b1 = *(const float4*)&B[(size_t)(n0 + lr + 64) * DDIM + lc];
        As[0][lc + 0][lr] = a0.x; As[0][lc + 1][lr] = a0.y; As[0][lc + 2][lr] = a0.z; As[0][lc + 3][lr] = a0.w;
        As[0][lc + 0][lr + 64] = a1.x; As[0][lc + 1][lr + 64] = a1.y; As[0][lc + 2][lr + 64] = a1.z; As[0][lc + 3][lr + 64] = a1.w;
        Bs[0][lc + 0][lr] = b0.x; Bs[0][lc + 1][lr] = b0.y; Bs[0][lc + 2][lr] = b0.z; Bs[0][lc + 3][lr] = b0.w;
        Bs[0][lc + 0][lr + 64] = b1.x; Bs[0][lc + 1][lr + 64] = b1.y; Bs[0][lc + 2][lr + 64] = b1.z; Bs[0][lc + 3][lr + 64] = b1.w;
    }
    __syncthreads();

    for (int ch = 0; ch < DDIM / 16; ch++) {
        const int cur = ch & 1;
        const bool has = (ch + 1) < DDIM / 16;
        float4 na0, na1, nb0, nb1;
        if (has) {
            const int kc = (ch + 1) * 16;
            na0 = *(const float4*)&A[(size_t)(m0 + lr) * DDIM + kc + lc];
            na1 = *(const float4*)&A[(size_t)(m0 + lr + 64) * DDIM + kc + lc];
            nb0 = *(const float4*)&B[(size_t)(n0 + lr) * DDIM + kc + lc];
            nb1 = *(const float4*)&B[(size_t)(n0 + lr + 64) * DDIM + kc + lc];
        }
#pragma unroll
        for (int kk = 0; kk < 16; kk++) {
            const float4 av0 = *(const float4*)&As[cur][kk][ty * 4];
            const float4 av1 = *(const float4*)&As[cur][kk][ty * 4 + 64];
            const ulonglong2 bp0 = *(const ulonglong2*)&Bs[cur][kk][tx * 4];
            const ulonglong2 bp1 = *(const ulonglong2*)&Bs[cur][kk][tx * 4 + 64];
            QMMA()
        }
        if (has) {
            const int nxt = cur ^ 1;
            As[nxt][lc + 0][lr] = na0.x; As[nxt][lc + 1][lr] = na0.y; As[nxt][lc + 2][lr] = na0.z; As[nxt][lc + 3][lr] = na0.w;
            As[nxt][lc + 0][lr + 64] = na1.x; As[nxt][lc + 1][lr + 64] = na1.y; As[nxt][lc + 2][lr + 64] = na1.z; As[nxt][lc + 3][lr + 64] = na1.w;
            Bs[nxt][lc + 0][lr] = nb0.x; Bs[nxt][lc + 1][lr] = nb0.y; Bs[nxt][lc + 2][lr] = nb0.z; Bs[nxt][lc + 3][lr] = nb0.w;
            Bs[nxt][lc + 0][lr + 64] = nb1.x; Bs[nxt][lc + 1][lr + 64] = nb1.y; Bs[nxt][lc + 2][lr + 64] = nb1.z; Bs[nxt][lc + 3][lr + 64] = nb1.w;
        }
        __syncthreads();
    }

#pragma unroll
    for (int i = 0; i < 8; i++) {
        const int m = m0 + ((i < 4) ? (ty * 4 + i) : (64 + ty * 4 + i - 4));
        float f[8];
        UNPK(f[0], f[1], acc2[i][0]); UNPK(f[2], f[3], acc2[i][1]);
        UNPK(f[4], f[5], acc2[i][2]); UNPK(f[6], f[7], acc2[i][3]);
        float4 v0 = make_float4(f[0] * ATT_SCALE, f[1] * ATT_SCALE, f[2] * ATT_SCALE, f[3] * ATT_SCALE);
        float4 v1 = make_float4(f[4] * ATT_SCALE, f[5] * ATT_SCALE, f[6] * ATT_SCALE, f[7] * ATT_SCALE);
        *(float4*)&C[(size_t)m * NQ + n0 + tx * 4] = v0;
        *(float4*)&C[(size_t)m * NQ + n0 + 64 + tx * 4] = v1;
    }
}

// ---------------------------------------------------------------------------
// Kernel 3: row softmax over g_S, in place. One block per 4 rows.
// ---------------------------------------------------------------------------
__global__ __launch_bounds__(256) void softmax_kernel()
{
    __shared__ float redm[8];
    __shared__ float reds[8];
    const int tid = threadIdx.x;
    for (int r = 0; r < 4; r++) {
        float* S = g_S + (size_t)(blockIdx.x * 4 + r) * NQ;
        float v0 = S[tid], v1 = S[tid + 256], v2 = S[tid + 512], v3 = S[tid + 768];
        float m = fmaxf(fmaxf(v0, v1), fmaxf(v2, v3));
#pragma unroll
        for (int o = 16; o > 0; o >>= 1) m = fmaxf(m, __shfl_xor_sync(0xffffffffu, m, o));
        if ((tid & 31) == 0) redm[tid >> 5] = m;
        __syncthreads();
        m = redm[0];
#pragma unroll
        for (int i = 1; i < 8; i++) m = fmaxf(m, redm[i]);
        v0 = __expf(v0 - m); v1 = __expf(v1 - m); v2 = __expf(v2 - m); v3 = __expf(v3 - m);
        float sum = v0 + v1 + v2 + v3;
#pragma unroll
        for (int o = 16; o > 0; o >>= 1) sum += __shfl_xor_sync(0xffffffffu, sum, o);
        if ((tid & 31) == 0) reds[tid >> 5] = sum;
        __syncthreads();
        sum = 0.f;
#pragma unroll
        for (int i = 0; i < 8; i++) sum += reds[i];
        const float inv = 1.0f / sum;
        S[tid] = v0 * inv; S[tid + 256] = v1 * inv; S[tid + 512] = v2 * inv; S[tid + 768] = v3 * inv;
        __syncthreads();
    }
}

// ---------------------------------------------------------------------------
// Kernel 4: Y = P @ V. 128x128 tile, BK=16, 256 thr, f32x2, double-buffered.
// (256,2) for 2 CTAs/SM. Epilogue fuses grid2im scatter into aliased g_Q.
// ---------------------------------------------------------------------------
__global__ __launch_bounds__(256, 2) void pv_kernel()
{
    __shared__ float As[2][16][132];
    __shared__ float Bs[2][16][132];
    const int h  = blockIdx.z;
    const int m0 = blockIdx.y * 128;
    const int n0 = blockIdx.x * 128;
    const float* A = g_S + (size_t)h * NQ * NQ;
    const float* B = g_V + (size_t)h * NQ * DDIM;
    float* img = g_Q;   // g_Q dead after qk_kernel

    const int tid = threadIdx.x;
    const int lr = tid >> 2;
    const int lc = (tid & 3) * 4;
    const int br = tid >> 5;             // 0..7
    const int bc = (tid & 31) * 4;       // 0..124
    const int tx = tid & 15, ty = tid >> 4;

    u64 acc2[8][4];
#pragma unroll
    for (int i = 0; i < 8; i++)
#pragma unroll
        for (int j = 0; j < 4; j++) acc2[i][j] = 0ull;

    // prologue: stage chunk 0
    {
        const float4 a0 = *(const float4*)&A[(size_t)(m0 + lr) * NQ + lc];
        const float4 a1 = *(const float4*)&A[(size_t)(m0 + lr + 64) * NQ + lc];
        const float4 bA = *(const float4*)&B[(size_t)br * DDIM + n0 + bc];
        const float4 bB = *(const float4*)&B[(size_t)(br + 8) * DDIM + n0 + bc];
        As[0][lc + 0][lr] = a0.x; As[0][lc + 1][lr] = a0.y; As[0][lc + 2][lr] = a0.z; As[0][lc + 3][lr] = a0.w;
        As[0][lc + 0][lr + 64] = a1.x; As[0][lc + 1][lr + 64] = a1.y; As[0][lc + 2][lr + 64] = a1.z; As[0][lc + 3][lr + 64] = a1.w;
        *(float4*)&Bs[0][br][bc] = bA;
        *(float4*)&Bs[0][br + 8][bc] = bB;
    }
    __syncthreads();

    for (int ch = 0; ch < NQ / 16; ch++) {
        const int cur = ch & 1;
        const bool has = (ch + 1) < NQ / 16;
        float4 na0, na1, nbA, nbB;
        if (has) {
            const int kc = (ch + 1) * 16;
            na0 = *(const float4*)&A[(size_t)(m0 + lr) * NQ + kc + lc];
            na1 = *(const float4*)&A[(size_t)(m0 + lr + 64) * NQ + kc + lc];
            nbA = *(const float4*)&B[(size_t)(kc + br) * DDIM + n0 + bc];
            nbB = *(const float4*)&B[(size_t)(kc + br + 8) * DDIM + n0 + bc];
        }
#pragma unroll
        for (int kk = 0; kk < 16; kk++) {
            const float4 av0 = *(const float4*)&As[cur][kk][ty * 4];
            const float4 av1 = *(const float4*)&As[cur][kk][ty * 4 + 64];
            const ulonglong2 bp0 = *(const ulonglong2*)&Bs[cur][kk][tx * 4];
            const ulonglong2 bp1 = *(const ulonglong2*)&Bs[cur][kk][tx * 4 + 64];
            QMMA()
        }
        if (has) {
            const int nxt = cur ^ 1;
            As[nxt][lc + 0][lr] = na0.x; As[nxt][lc + 1][lr] = na0.y; As[nxt][lc + 2][lr] = na0.z; As[nxt][lc + 3][lr] = na0.w;
            As[nxt][lc + 0][lr + 64] = na1.x; As[nxt][lc + 1][lr + 64] = na1.y; As[nxt][lc + 2][lr + 64] = na1.z; As[nxt][lc + 3][lr + 64] = na1.w;
            *(float4*)&Bs[nxt][br][bc] = nbA;
            *(float4*)&Bs[nxt][br + 8][bc] = nbB;
        }
        __syncthreads();
    }

    // grid2im scatter
    const int bt = h >> 3, nh = h & 7;
#pragma unroll
    for (int i = 0; i < 8; i++) {
        const int q  = m0 + ((i < 4) ? (ty * 4 + i) : (64 + ty * 4 + i - 4));
        const int hi = q >> 5, wi = q & 31;
        float f[8];
        UNPK(f[0], f[1], acc2[i][0]); UNPK(f[2], f[3], acc2[i][1]);
        UNPK(f[4], f[5], acc2[i][2]); UNPK(f[6], f[7], acc2[i][3]);
#pragma unroll
        for (int j = 0; j < 8; j++) {
            const int d = n0 + ((j < 4) ? (tx * 4 + j) : (64 + tx * 4 + j - 4));
            const int cl = d >> 6, r = d & 63;
            const int pgi = r >> 3, pgj = r & 7;
            const int co = nh * 8 + cl;
            img[((bt * COUT + co) * HH + (pgi * HG + hi)) * WW + (pgj * WG + wi)] = f[j];
        }
    }
}

// ---------------------------------------------------------------------------
// Kernel 5: out = img + conv3x3(img, wo) + bo ; 16 co per thread, f32x2.
// ---------------------------------------------------------------------------
__global__ __launch_bounds__(256) void oconv_kernel(
    const float* __restrict__ wo, const float* __restrict__ bo,
    float* __restrict__ out)
{
    __shared__ float patch[8 * 18 * 34];
    __shared__ float Ws[72 * 16];        // [rem = cil*9+dd][co], 16 co

    const int bz  = blockIdx.z;
    const int bt  = bz >> 2;
    const int co0 = (bz & 3) * 16;
    const int h0  = blockIdx.y * 16;
    const int w0  = blockIdx.x * 32;

    const int tid = threadIdx.x;
    const int th  = tid >> 4;
    const int tw  = tid & 15;

    u64 acc2[8][2];                     // [co-pair][pos: tw, tw+16]
#pragma unroll
    for (int c = 0; c < 8; c++) { acc2[c][0] = 0ull; acc2[c][1] = 0ull; }

    const float* img = g_Q + (size_t)bt * COUT * HH * WW;

    for (int cc = 0; cc < 8; cc++) {
        const int ci0 = cc * 8;
        __syncthreads();
        for (int i = tid; i < 8 * 18 * 34; i += 256) {
            const int ci = i / 612;
            const int rem = i - ci * 612;
            const int r = rem / 34;
            const int c = rem - r * 34;
            const int gh = h0 - 1 + r, gw = w0 - 1 + c;
            float v = 0.f;
            if (gh >= 0 && gh < HH && gw >= 0 && gw < WW)
                v = img[((ci0 + ci) * HH + gh) * WW + gw];
            patch[i] = v;
        }
        for (int i = tid; i < 72 * 16; i += 256) {
            const int co = i & 15;
            const int rem = i >> 4;
            Ws[rem * 16 + co] = wo[(co0 + co) * KCONV + ci0 * 9 + rem];
        }
        __syncthreads();
#pragma unroll
        for (int dy = 0; dy < 3; dy++) {
#pragma unroll
            for (int dx = 0; dx < 3; dx++) {
#pragma unroll
                for (int ci = 0; ci < 8; ci++) {
                    const float p0 = patch[ci * 612 + (th + dy) * 34 + (tw + dx)];
                    const float p1 = patch[ci * 612 + (th + dy) * 34 + (tw + 16 + dx)];
                    const float* wrow = &Ws[(ci * 9 + dy * 3 + dx) * 16];
                    const ulonglong2 wA = *(const ulonglong2*)&wrow[0];
                    const ulonglong2 wB = *(const ulonglong2*)&wrow[4];
                    const ulonglong2 wC = *(const ulonglong2*)&wrow[8];
                    const ulonglong2 wD = *(const ulonglong2*)&wrow[12];
                    CFMA(0, p0) CFMA(1, p1)
                }
            }
        }
    }
#pragma unroll
    for (int c = 0; c < 8; c++) {
        float a00, a10, a01, a11;
        UNPK(a00, a10, acc2[c][0]);   // co0+2c, co0+2c+1 at pos tw
        UNPK(a01, a11, acc2[c][1]);   // at pos tw+16
        const int coA = co0 + 2 * c;
        const int coB = coA + 1;
        const float bA = bo[coA], bB = bo[coB];
        const size_t oA = ((size_t)(bt * COUT + coA) * HH + (h0 + th)) * WW + (w0 + tw);
        const size_t oB = ((size_t)(bt * COUT + coB) * HH + (h0 + th)) * WW + (w0 + tw);
        out[oA]      = a00 + bA + img[(coA * HH + h0 + th) * WW + w0 + tw];
        out[oA + 16] = a01 + bA + img[(coA * HH + h0 + th) * WW + w0 + tw + 16];
        out[oB]      = a10 + bB + img[(coB * HH + h0 + th) * WW + w0 + tw];
        out[oB + 16] = a11 + bB + img[(coB * HH + h0 + th) * WW + w0 + tw + 16];
    }
}

// ---------------------------------------------------------------------------
extern "C" void kernel_launch(void* const* d_in, const int* in_sizes, int n_in,
                              void* d_out, int out_size)
{
    (void)in_sizes; (void)n_in; (void)out_size;
    const float* x  = (const float*)d_in[0];
    const float* wq = (const float*)d_in[1];
    const float* bq = (const float*)d_in[2];
    const float* wk = (const float*)d_in[3];
    const float* bk = (const float*)d_in[4];
    const float* wv = (const float*)d_in[5];
    const float* bv = (const float*)d_in[6];
    const float* wo = (const float*)d_in[7];
    const float* bo = (const float*)d_in[8];
    float* out = (float*)d_out;

    qkv_conv_kernel<<<dim3(256, 3), 512>>>(x, wq, bq, wk, bk, wv, bv);
    qk_kernel<<<dim3(8, 8, 64), 256>>>();
    softmax_kernel<<<16384, 256>>>();
    pv_kernel<<<dim3(4, 8, 64), 256>>>();
    oconv_kernel<<<dim3(8, 16, 32), 256>>>(wo, bo, out);
}

// round 14
// speedup vs baseline: 1.9042x; 1.0453x over previous
#include <cuda_runtime.h>
#include <cuda_bf16.h>
#include <math.h>
#include <stdint.h>

// Problem constants
#define CIN    64
#define HH     256
#define WW     256
#define COUT   64
#define NHD    8
#define HG     32
#define WG     32
#define NQ     1024
#define DDIM   512
#define NBT    8
#define NHEADS 64
#define KCONV  576
#define ATT_SCALE 0.044194173824159216f  // 1/sqrt(512)

typedef unsigned long long u64;

// ---------------- f32x2 helpers (conv kernels) ----------------
#define FMA2(d, a, b) \
    asm("fma.rn.f32x2 %0, %1, %2, %0;" : "+l"(d) : "l"(a), "l"(b))
#define DUP2(d, s) \
    asm("mov.b64 %0, {%1, %1};" : "=l"(d) : "r"(__float_as_uint(s)))
#define PK2(d, lo, hi) \
    asm("mov.b64 %0, {%1, %2};" : "=l"(d) : "r"(__float_as_uint(lo)), "r"(__float_as_uint(hi)))
#define UNPK(lo, hi, v) \
    { unsigned _l, _h; asm("mov.b64 {%0, %1}, %2;" : "=r"(_l), "=r"(_h) : "l"(v)); \
      lo = __uint_as_float(_l); hi = __uint_as_float(_h); }

#define CFMA(u, P) { u64 _pd; DUP2(_pd, P);                                  \
    FMA2(acc2[0][u], wA.x, _pd); FMA2(acc2[1][u], wA.y, _pd);                \
    FMA2(acc2[2][u], wB.x, _pd); FMA2(acc2[3][u], wB.y, _pd);                \
    FMA2(acc2[4][u], wC.x, _pd); FMA2(acc2[5][u], wC.y, _pd);                \
    FMA2(acc2[6][u], wD.x, _pd); FMA2(acc2[7][u], wD.y, _pd); }

// ---------------- warp-level tensor core helpers (sm_80 PTX) ----------------
__device__ __forceinline__ uint32_t smem_u32(const void* p) {
    uint32_t a;
    asm("{ .reg .u64 t; cvta.to.shared.u64 t, %1; cvt.u32.u64 %0, t; }" : "=r"(a) : "l"(p));
    return a;
}
#define LDSM4(r0, r1, r2, r3, addr) \
    asm volatile("ldmatrix.sync.aligned.m8n8.x4.shared.b16 {%0,%1,%2,%3}, [%4];" \
                 : "=r"(r0), "=r"(r1), "=r"(r2), "=r"(r3) : "r"(addr))
#define MMA16816(c, a, b0v, b1v) \
    asm volatile("mma.sync.aligned.m16n8k16.row.col.f32.bf16.bf16.f32 " \
                 "{%0,%1,%2,%3}, {%4,%5,%6,%7}, {%8,%9}, {%0,%1,%2,%3};" \
                 : "+f"((c)[0]), "+f"((c)[1]), "+f"((c)[2]), "+f"((c)[3]) \
                 : "r"((a)[0]), "r"((a)[1]), "r"((a)[2]), "r"((a)[3]), \
                   "r"(b0v), "r"(b1v))

// ---------------- scratch (device globals; no allocations) ----------------
__device__ float g_S[NHEADS * NQ * NQ];                 // S (fp32); later reused as img
__device__ __nv_bfloat16 g_Qhi[NHEADS * NQ * DDIM];
__device__ __nv_bfloat16 g_Qlo[NHEADS * NQ * DDIM];
__device__ __nv_bfloat16 g_Khi[NHEADS * NQ * DDIM];
__device__ __nv_bfloat16 g_Klo[NHEADS * NQ * DDIM];
__device__ __nv_bfloat16 g_Vhi[NHEADS * NQ * DDIM];
__device__ __nv_bfloat16 g_Vlo[NHEADS * NQ * DDIM];
__device__ __nv_bfloat16 g_Vthi[NHEADS * DDIM * NQ];    // V^T [d][q]
__device__ __nv_bfloat16 g_Vtlo[NHEADS * DDIM * NQ];
__device__ __nv_bfloat16 g_Phi[NHEADS * NQ * NQ];
__device__ __nv_bfloat16 g_Plo[NHEADS * NQ * NQ];

__device__ __forceinline__ unsigned bfpack(__nv_bfloat16 a, __nv_bfloat16 b) {
    unsigned short ua = *(unsigned short*)&a, ub = *(unsigned short*)&b;
    return (unsigned)ua | ((unsigned)ub << 16);
}

// ---------------------------------------------------------------------------
// Kernel 1: fused QKV grid-conv (f32x2), emits bf16 hi/lo split outputs.
// ---------------------------------------------------------------------------
__global__ __launch_bounds__(512) void qkv_conv_kernel(
    const float* __restrict__ x,
    const float* __restrict__ wq, const float* __restrict__ bq,
    const float* __restrict__ wk, const float* __restrict__ bk,
    const float* __restrict__ wv, const float* __restrict__ bv)
{
    __shared__ float Wc[72 * 68];
    __shared__ float pat[8][8][100];

    const int conv = blockIdx.y;
    const float* wsrc = (conv == 0) ? wq : (conv == 1) ? wk : wv;
    const float* bsrc = (conv == 0) ? bq : (conv == 1) ? bk : bv;
    __nv_bfloat16* dsth = (conv == 0) ? g_Qhi : (conv == 1) ? g_Khi : g_Vhi;
    __nv_bfloat16* dstl = (conv == 0) ? g_Qlo : (conv == 1) ? g_Klo : g_Vlo;

    const int tid = threadIdx.x;
    const int s   = tid >> 6;
    const int t2  = tid & 63;
    const int cog = t2 >> 4;
    const int pt  = t2 & 15;
    const int gi  = pt >> 1;
    const int gjb = (pt & 1) * 4;
    const int co0 = cog * 16;

    u64 bias2[8];
#pragma unroll
    for (int c = 0; c < 8; c++) PK2(bias2[c], bsrc[co0 + 2 * c], bsrc[co0 + 2 * c + 1]);

    for (int i = tid; i < 8 * 8 * 100; i += 512) ((float*)pat)[i] = 0.f;

    for (int g = 0; g < 4; g++) {
        const int qbase = blockIdx.x * 32 + g * 8;
        const int sg = qbase + s;
        const int bt = sg >> 10;
        const int q  = sg & 1023;

        u64 acc2[8][4];
#pragma unroll
        for (int c = 0; c < 8; c++)
#pragma unroll
            for (int u = 0; u < 4; u++) acc2[c][u] = bias2[c];

        for (int cc = 0; cc < 8; cc++) {
            __syncthreads();
            for (int i = tid; i < 4608; i += 512) {
                const int co_s = i / 72;
                const int kl   = i - co_s * 72;
                Wc[kl * 68 + co_s] = wsrc[co_s * KCONV + cc * 72 + kl];
            }
            for (int i = tid; i < 4096; i += 512) {
                const int ss  = i & 7;
                int r = i >> 3;
                const int pgj = r & 7; r >>= 3;
                const int pgi = r & 7;
                const int cil = r >> 3;
                const int sg2 = qbase + ss;
                const int bt2 = sg2 >> 10;
                const int q2  = sg2 & 1023;
                const int hi2 = q2 >> 5, wi2 = q2 & 31;
                pat[ss][cil][(pgi + 1) * 10 + pgj + 1] =
                    x[((bt2 * CIN + cc * 8 + cil) * HH + (pgi * HG + hi2)) * WW + pgj * WG + wi2];
            }
            __syncthreads();
#pragma unroll
            for (int dy = 0; dy < 3; dy++) {
#pragma unroll
                for (int dx = 0; dx < 3; dx++) {
#pragma unroll
                    for (int cl = 0; cl < 8; cl++) {
                        const float* prow = &pat[s][cl][(gi + dy) * 10 + gjb + dx];
                        const float p0 = prow[0], p1 = prow[1], p2 = prow[2], p3 = prow[3];
                        const float* wrow = &Wc[(cl * 9 + dy * 3 + dx) * 68 + co0];
                        const ulonglong2 wA = *(const ulonglong2*)&wrow[0];
                        const ulonglong2 wB = *(const ulonglong2*)&wrow[4];
                        const ulonglong2 wC = *(const ulonglong2*)&wrow[8];
                        const ulonglong2 wD = *(const ulonglong2*)&wrow[12];
                        CFMA(0, p0) CFMA(1, p1) CFMA(2, p2) CFMA(3, p3)
                    }
                }
            }
        }
        float accf[16][4];
#pragma unroll
        for (int c = 0; c < 8; c++)
#pragma unroll
            for (int u = 0; u < 4; u++) { UNPK(accf[2 * c][u], accf[2 * c + 1][u], acc2[c][u]); }
#pragma unroll
        for (int i = 0; i < 16; i++) {
            const int co = co0 + i;
            const int n = co >> 3, cl = co & 7;
            const size_t base = ((size_t)(bt * NHD + n) * NQ + q) * DDIM + cl * 64 + pt * 4;
            __nv_bfloat16 h0 = __float2bfloat16_rn(accf[i][0]);
            __nv_bfloat16 h1 = __float2bfloat16_rn(accf[i][1]);
            __nv_bfloat16 h2 = __float2bfloat16_rn(accf[i][2]);
            __nv_bfloat16 h3 = __float2bfloat16_rn(accf[i][3]);
            uint2 vh; vh.x = bfpack(h0, h1); vh.y = bfpack(h2, h3);
            *(uint2*)&dsth[base] = vh;
            __nv_bfloat16 l0 = __float2bfloat16_rn(accf[i][0] - __bfloat162float(h0));
            __nv_bfloat16 l1 = __float2bfloat16_rn(accf[i][1] - __bfloat162float(h1));
            __nv_bfloat16 l2 = __float2bfloat16_rn(accf[i][2] - __bfloat162float(h2));
            __nv_bfloat16 l3 = __float2bfloat16_rn(accf[i][3] - __bfloat162float(h3));
            uint2 vl; vl.x = bfpack(l0, l1); vl.y = bfpack(l2, l3);
            *(uint2*)&dstl[base] = vl;
        }
    }
}

// ---------------------------------------------------------------------------
// Kernel 2: V^T transpose (bf16 hi+lo), 64x64 tiles via smem.
// ---------------------------------------------------------------------------
__global__ __launch_bounds__(256) void vt_kernel()
{
    __shared__ __nv_bfloat16 sh[64][66];
    __shared__ __nv_bfloat16 sl[64][66];
    const int tid = threadIdx.x;
    const int h  = blockIdx.z;
    const int q0 = blockIdx.y * 64;
    const int d0 = blockIdx.x * 64;
    const __nv_bfloat16* Vh = g_Vhi + (size_t)h * NQ * DDIM;
    const __nv_bfloat16* Vl = g_Vlo + (size_t)h * NQ * DDIM;
    for (int i = tid; i < 4096; i += 256) {
        const int qq = i >> 6, dd = i & 63;
        sh[qq][dd] = Vh[(size_t)(q0 + qq) * DDIM + d0 + dd];
        sl[qq][dd] = Vl[(size_t)(q0 + qq) * DDIM + d0 + dd];
    }
    __syncthreads();
    __nv_bfloat16* Th = g_Vthi + (size_t)h * DDIM * NQ;
    __nv_bfloat16* Tl = g_Vtlo + (size_t)h * DDIM * NQ;
    for (int i = tid; i < 4096; i += 256) {
        const int dd = i >> 6, qq = i & 63;
        Th[(size_t)(d0 + dd) * NQ + q0 + qq] = sh[qq][dd];
        Tl[(size_t)(d0 + dd) * NQ + q0 + qq] = sl[qq][dd];
    }
}

// ---------------------------------------------------------------------------
// HMMA GEMM core: 128x128 CTA tile, 8 warps (4 m x 2 n), per-warp 32x64.
// A[m][k], B[n][k] bf16 hi/lo tiles in smem (BK=32, rows padded to 40 elems).
// 3 split products: Ah*Bh + Ah*Bl + Al*Bh, fp32 accumulate in registers.
// ---------------------------------------------------------------------------
#define PADK 40

struct MmaAcc { float c[2][8][4]; };

__device__ __forceinline__ void stage_tile(__nv_bfloat16* sm,
                                           const __nv_bfloat16* g, size_t ld,
                                           int kc, int tid) {
    for (int i = tid; i < 512; i += 256) {
        const int row = i >> 2, seg = i & 3;
        const uint4 v = *(const uint4*)(g + (size_t)row * ld + kc + seg * 8);
        *(uint4*)(sm + row * PADK + seg * 8) = v;
    }
}

__device__ __forceinline__ void mma_chunk(MmaAcc& A_, uint32_t aAh, uint32_t aAl,
                                          uint32_t aBh, uint32_t aBl,
                                          int wm, int wn, int lane) {
    const int lr = lane & 15;         // ldmatrix row select
    const int lc = (lane >> 4) * 8;   // ldmatrix col select
#pragma unroll
    for (int p = 0; p < 3; p++) {
        const uint32_t aA = (p == 2) ? aAl : aAh;
        const uint32_t aB = (p == 1) ? aBl : aBh;
#pragma unroll
        for (int ks = 0; ks < 2; ks++) {
            const int k0 = ks * 16;
            uint32_t af[2][4];
#pragma unroll
            for (int mf = 0; mf < 2; mf++) {
                const uint32_t ad = aA + ((wm * 32 + mf * 16 + lr) * PADK + k0 + lc) * 2;
                LDSM4(af[mf][0], af[mf][1], af[mf][2], af[mf][3], ad);
            }
#pragma unroll
            for (int nq = 0; nq < 4; nq++) {
                uint32_t b0, b1, b2, b3;
                const uint32_t bd = aB + ((wn * 64 + nq * 16 + lr) * PADK + k0 + lc) * 2;
                LDSM4(b0, b1, b2, b3, bd);
#pragma unroll
                for (int mf = 0; mf < 2; mf++) {
                    MMA16816(A_.c[mf][nq * 2 + 0], af[mf], b0, b2);
                    MMA16816(A_.c[mf][nq * 2 + 1], af[mf], b1, b3);
                }
            }
        }
    }
}

// ---------------------------------------------------------------------------
// Kernel 3: qk via HMMA. S = scale * (Qhi+Qlo)@(Khi+Klo)^T (lo*lo dropped).
// ---------------------------------------------------------------------------
__global__ __launch_bounds__(256) void qk_mma_kernel()
{
    __shared__ __nv_bfloat16 smAh[128 * PADK];
    __shared__ __nv_bfloat16 smAl[128 * PADK];
    __shared__ __nv_bfloat16 smBh[128 * PADK];
    __shared__ __nv_bfloat16 smBl[128 * PADK];

    const int tid = threadIdx.x, wid = tid >> 5, lane = tid & 31;
    const int wm = wid & 3, wn = wid >> 2;
    const int h = blockIdx.z, m0 = blockIdx.y * 128, n0 = blockIdx.x * 128;

    const __nv_bfloat16* Ah = g_Qhi + (size_t)h * NQ * DDIM + (size_t)m0 * DDIM;
    const __nv_bfloat16* Al = g_Qlo + (size_t)h * NQ * DDIM + (size_t)m0 * DDIM;
    const __nv_bfloat16* Bh = g_Khi + (size_t)h * NQ * DDIM + (size_t)n0 * DDIM;
    const __nv_bfloat16* Bl = g_Klo + (size_t)h * NQ * DDIM + (size_t)n0 * DDIM;

    const uint32_t aAh = smem_u32(smAh), aAl = smem_u32(smAl);
    const uint32_t aBh = smem_u32(smBh), aBl = smem_u32(smBl);

    MmaAcc acc;
#pragma unroll
    for (int mf = 0; mf < 2; mf++)
#pragma unroll
        for (int nf = 0; nf < 8; nf++)
#pragma unroll
            for (int e = 0; e < 4; e++) acc.c[mf][nf][e] = 0.f;

    for (int c = 0; c < DDIM / 32; c++) {
        const int kc = c * 32;
        __syncthreads();
        stage_tile(smAh, Ah, DDIM, kc, tid);
        stage_tile(smAl, Al, DDIM, kc, tid);
        stage_tile(smBh, Bh, DDIM, kc, tid);
        stage_tile(smBl, Bl, DDIM, kc, tid);
        __syncthreads();
        mma_chunk(acc, aAh, aAl, aBh, aBl, wm, wn, lane);
    }

    float* C = g_S + (size_t)h * NQ * NQ;
    const int r = lane >> 2, c2 = (lane & 3) * 2;
#pragma unroll
    for (int mf = 0; mf < 2; mf++) {
        const int m = m0 + wm * 32 + mf * 16 + r;
#pragma unroll
        for (int nf = 0; nf < 8; nf++) {
            const int n = n0 + wn * 64 + nf * 8 + c2;
            float2 v0 = make_float2(acc.c[mf][nf][0] * ATT_SCALE, acc.c[mf][nf][1] * ATT_SCALE);
            float2 v1 = make_float2(acc.c[mf][nf][2] * ATT_SCALE, acc.c[mf][nf][3] * ATT_SCALE);
            *(float2*)&C[(size_t)m * NQ + n] = v0;
            *(float2*)&C[(size_t)(m + 8) * NQ + n] = v1;
        }
    }
}

// ---------------------------------------------------------------------------
// Kernel 4: row softmax over g_S; writes P as bf16 hi/lo split.
// ---------------------------------------------------------------------------
__global__ __launch_bounds__(256) void softmax_kernel()
{
    __shared__ float redm[8];
    __shared__ float reds[8];
    const int tid = threadIdx.x;
    for (int r = 0; r < 4; r++) {
        const size_t row = (size_t)blockIdx.x * 4 + r;
        float* S = g_S + row * NQ;
        float v0 = S[tid], v1 = S[tid + 256], v2 = S[tid + 512], v3 = S[tid + 768];
        float m = fmaxf(fmaxf(v0, v1), fmaxf(v2, v3));
#pragma unroll
        for (int o = 16; o > 0; o >>= 1) m = fmaxf(m, __shfl_xor_sync(0xffffffffu, m, o));
        if ((tid & 31) == 0) redm[tid >> 5] = m;
        __syncthreads();
        m = redm[0];
#pragma unroll
        for (int i = 1; i < 8; i++) m = fmaxf(m, redm[i]);
        v0 = __expf(v0 - m); v1 = __expf(v1 - m); v2 = __expf(v2 - m); v3 = __expf(v3 - m);
        float sum = v0 + v1 + v2 + v3;
#pragma unroll
        for (int o = 16; o > 0; o >>= 1) sum += __shfl_xor_sync(0xffffffffu, sum, o);
        if ((tid & 31) == 0) reds[tid >> 5] = sum;
        __syncthreads();
        sum = 0.f;
#pragma unroll
        for (int i = 0; i < 8; i++) sum += reds[i];
        const float inv = 1.0f / sum;
        __nv_bfloat16* Ph = g_Phi + row * NQ;
        __nv_bfloat16* Pl = g_Plo + row * NQ;
        const float p[4] = {v0 * inv, v1 * inv, v2 * inv, v3 * inv};
#pragma unroll
        for (int k = 0; k < 4; k++) {
            const int idx = tid + k * 256;
            __nv_bfloat16 hh = __float2bfloat16_rn(p[k]);
            Ph[idx] = hh;
            Pl[idx] = __float2bfloat16_rn(p[k] - __bfloat162float(hh));
        }
        __syncthreads();
    }
}

// ---------------------------------------------------------------------------
// Kernel 5: pv via HMMA. Y = (Phi+Plo)@(Vt_hi+Vt_lo)^T (lo*lo dropped).
// Epilogue: grid2im scatter into img (aliased on g_S, dead after softmax).
// ---------------------------------------------------------------------------
__global__ __launch_bounds__(256) void pv_mma_kernel()
{
    __shared__ __nv_bfloat16 smAh[128 * PADK];
    __shared__ __nv_bfloat16 smAl[128 * PADK];
    __shared__ __nv_bfloat16 smBh[128 * PADK];
    __shared__ __nv_bfloat16 smBl[128 * PADK];

    const int tid = threadIdx.x, wid = tid >> 5, lane = tid & 31;
    const int wm = wid & 3, wn = wid >> 2;
    const int h = blockIdx.z, m0 = blockIdx.y * 128, n0 = blockIdx.x * 128;

    const __nv_bfloat16* Ah = g_Phi + (size_t)h * NQ * NQ + (size_t)m0 * NQ;
    const __nv_bfloat16* Al = g_Plo + (size_t)h * NQ * NQ + (size_t)m0 * NQ;
    const __nv_bfloat16* Bh = g_Vthi + (size_t)h * DDIM * NQ + (size_t)n0 * NQ;
    const __nv_bfloat16* Bl = g_Vtlo + (size_t)h * DDIM * NQ + (size_t)n0 * NQ;

    const uint32_t aAh = smem_u32(smAh), aAl = smem_u32(smAl);
    const uint32_t aBh = smem_u32(smBh), aBl = smem_u32(smBl);

    MmaAcc acc;
#pragma unroll
    for (int mf = 0; mf < 2; mf++)
#pragma unroll
        for (int nf = 0; nf < 8; nf++)
#pragma unroll
            for (int e = 0; e < 4; e++) acc.c[mf][nf][e] = 0.f;

    for (int c = 0; c < NQ / 32; c++) {
        const int kc = c * 32;
        __syncthreads();
        stage_tile(smAh, Ah, NQ, kc, tid);
        stage_tile(smAl, Al, NQ, kc, tid);
        stage_tile(smBh, Bh, NQ, kc, tid);
        stage_tile(smBl, Bl, NQ, kc, tid);
        __syncthreads();
        mma_chunk(acc, aAh, aAl, aBh, aBl, wm, wn, lane);
    }

    float* img = g_S;   // alias: g_S dead after softmax
    const int bt = h >> 3, nh = h & 7;
    const int r = lane >> 2, c2 = (lane & 3) * 2;
#pragma unroll
    for (int mf = 0; mf < 2; mf++) {
#pragma unroll
        for (int half = 0; half < 2; half++) {
            const int q  = m0 + wm * 32 + mf * 16 + half * 8 + r;
            const int hi = q >> 5, wi = q & 31;
#pragma unroll
            for (int nf = 0; nf < 8; nf++) {
#pragma unroll
                for (int e = 0; e < 2; e++) {
                    const int d = n0 + wn * 64 + nf * 8 + c2 + e;
                    const int cl = d >> 6, rr = d & 63;
                    const int pgi = rr >> 3, pgj = rr & 7;
                    const int co = nh * 8 + cl;
                    img[((bt * COUT + co) * HH + (pgi * HG + hi)) * WW + (pgj * WG + wi)] =
                        acc.c[mf][nf][half * 2 + e];
                }
            }
        }
    }
}

// ---------------------------------------------------------------------------
// Kernel 6: out = img + conv3x3(img, wo) + bo ; 16 co per thread, f32x2.
// img aliased on g_S.
// ---------------------------------------------------------------------------
__global__ __launch_bounds__(256) void oconv_kernel(
    const float* __restrict__ wo, const float* __restrict__ bo,
    float* __restrict__ out)
{
    __shared__ float patch[8 * 18 * 34];
    __shared__ float Ws[72 * 16];

    const int bz  = blockIdx.z;
    const int bt  = bz >> 2;
    const int co0 = (bz & 3) * 16;
    const int h0  = blockIdx.y * 16;
    const int w0  = blockIdx.x * 32;

    const int tid = threadIdx.x;
    const int th  = tid >> 4;
    const int tw  = tid & 15;

    u64 acc2[8][2];
#pragma unroll
    for (int c = 0; c < 8; c++) { acc2[c][0] = 0ull; acc2[c][1] = 0ull; }

    const float* img = g_S + (size_t)bt * COUT * HH * WW;

    for (int cc = 0; cc < 8; cc++) {
        const int ci0 = cc * 8;
        __syncthreads();
        for (int i = tid; i < 8 * 18 * 34; i += 256) {
            const int ci = i / 612;
            const int rem = i - ci * 612;
            const int r = rem / 34;
            const int c = rem - r * 34;
            const int gh = h0 - 1 + r, gw = w0 - 1 + c;
            float v = 0.f;
            if (gh >= 0 && gh < HH && gw >= 0 && gw < WW)
                v = img[((ci0 + ci) * HH + gh) * WW + gw];
            patch[i] = v;
        }
        for (int i = tid; i < 72 * 16; i += 256) {
            const int co = i & 15;
            const int rem = i >> 4;
            Ws[rem * 16 + co] = wo[(co0 + co) * KCONV + ci0 * 9 + rem];
        }
        __syncthreads();
#pragma unroll
        for (int dy = 0; dy < 3; dy++) {
#pragma unroll
            for (int dx = 0; dx < 3; dx++) {
#pragma unroll
                for (int ci = 0; ci < 8; ci++) {
                    const float p0 = patch[ci * 612 + (th + dy) * 34 + (tw + dx)];
                    const float p1 = patch[ci * 612 + (th + dy) * 34 + (tw + 16 + dx)];
                    const float* wrow = &Ws[(ci * 9 + dy * 3 + dx) * 16];
                    const ulonglong2 wA = *(const ulonglong2*)&wrow[0];
                    const ulonglong2 wB = *(const ulonglong2*)&wrow[4];
                    const ulonglong2 wC = *(const ulonglong2*)&wrow[8];
                    const ulonglong2 wD = *(const ulonglong2*)&wrow[12];
                    CFMA(0, p0) CFMA(1, p1)
                }
            }
        }
    }
#pragma unroll
    for (int c = 0; c < 8; c++) {
        float a00, a10, a01, a11;
        UNPK(a00, a10, acc2[c][0]);
        UNPK(a01, a11, acc2[c][1]);
        const int coA = co0 + 2 * c;
        const int coB = coA + 1;
        const float bA = bo[coA], bB = bo[coB];
        const size_t oA = ((size_t)(bt * COUT + coA) * HH + (h0 + th)) * WW + (w0 + tw);
        const size_t oB = ((size_t)(bt * COUT + coB) * HH + (h0 + th)) * WW + (w0 + tw);
        out[oA]      = a00 + bA + img[(coA * HH + h0 + th) * WW + w0 + tw];
        out[oA + 16] = a01 + bA + img[(coA * HH + h0 + th) * WW + w0 + tw + 16];
        out[oB]      = a10 + bB + img[(coB * HH + h0 + th) * WW + w0 + tw];
        out[oB + 16] = a11 + bB + img[(coB * HH + h0 + th) * WW + w0 + tw + 16];
    }
}

// ---------------------------------------------------------------------------
extern "C" void kernel_launch(void* const* d_in, const int* in_sizes, int n_in,
                              void* d_out, int out_size)
{
    (void)in_sizes; (void)n_in; (void)out_size;
    const float* x  = (const float*)d_in[0];
    const float* wq = (const float*)d_in[1];
    const float* bq = (const float*)d_in[2];
    const float* wk = (const float*)d_in[3];
    const float* bk = (const float*)d_in[4];
    const float* wv = (const float*)d_in[5];
    const float* bv = (const float*)d_in[6];
    const float* wo = (const float*)d_in[7];
    const float* bo = (const float*)d_in[8];
    float* out = (float*)d_out;

    qkv_conv_kernel<<<dim3(256, 3), 512>>>(x, wq, bq, wk, bk, wv, bv);
    vt_kernel<<<dim3(8, 16, 64), 256>>>();
    qk_mma_kernel<<<dim3(8, 8, 64), 256>>>();
    softmax_kernel<<<16384, 256>>>();
    pv_mma_kernel<<<dim3(4, 8, 64), 256>>>();
    oconv_kernel<<<dim3(8, 16, 32), 256>>>(wo, bo, out);
}

// round 16
// speedup vs baseline: 2.1513x; 1.1297x over previous
#include <cuda_runtime.h>
#include <cuda_bf16.h>
#include <math.h>
#include <stdint.h>

// Problem constants
#define CIN    64
#define HH     256
#define WW     256
#define COUT   64
#define NHD    8
#define HG     32
#define WG     32
#define NQ     1024
#define DDIM   512
#define NBT    8
#define NHEADS 64
#define KCONV  576
#define ATT_SCALE 0.044194173824159216f  // 1/sqrt(512)

typedef unsigned long long u64;

// ---------------- f32x2 helpers (conv kernels) ----------------
#define FMA2(d, a, b) \
    asm("fma.rn.f32x2 %0, %1, %2, %0;" : "+l"(d) : "l"(a), "l"(b))
#define DUP2(d, s) \
    asm("mov.b64 %0, {%1, %1};" : "=l"(d) : "r"(__float_as_uint(s)))
#define PK2(d, lo, hi) \
    asm("mov.b64 %0, {%1, %2};" : "=l"(d) : "r"(__float_as_uint(lo)), "r"(__float_as_uint(hi)))
#define UNPK(lo, hi, v) \
    { unsigned _l, _h; asm("mov.b64 {%0, %1}, %2;" : "=r"(_l), "=r"(_h) : "l"(v)); \
      lo = __uint_as_float(_l); hi = __uint_as_float(_h); }

#define CFMA(u, P) { u64 _pd; DUP2(_pd, P);                                  \
    FMA2(acc2[0][u], wA.x, _pd); FMA2(acc2[1][u], wA.y, _pd);                \
    FMA2(acc2[2][u], wB.x, _pd); FMA2(acc2[3][u], wB.y, _pd);                \
    FMA2(acc2[4][u], wC.x, _pd); FMA2(acc2[5][u], wC.y, _pd);                \
    FMA2(acc2[6][u], wD.x, _pd); FMA2(acc2[7][u], wD.y, _pd); }

// ---------------- warp-level tensor core helpers (sm_80 PTX) ----------------
__device__ __forceinline__ uint32_t smem_u32(const void* p) {
    uint32_t a;
    asm("{ .reg .u64 t; cvta.to.shared.u64 t, %1; cvt.u32.u64 %0, t; }" : "=r"(a) : "l"(p));
    return a;
}
#define LDSM4(r0, r1, r2, r3, addr) \
    asm volatile("ldmatrix.sync.aligned.m8n8.x4.shared.b16 {%0,%1,%2,%3}, [%4];" \
                 : "=r"(r0), "=r"(r1), "=r"(r2), "=r"(r3) : "r"(addr))
#define MMA16816(c, a, b0v, b1v) \
    asm volatile("mma.sync.aligned.m16n8k16.row.col.f32.bf16.bf16.f32 " \
                 "{%0,%1,%2,%3}, {%4,%5,%6,%7}, {%8,%9}, {%0,%1,%2,%3};" \
                 : "+f"((c)[0]), "+f"((c)[1]), "+f"((c)[2]), "+f"((c)[3]) \
                 : "r"((a)[0]), "r"((a)[1]), "r"((a)[2]), "r"((a)[3]), \
                   "r"(b0v), "r"(b1v))
#define CP_ASYNC16(dst, src) \
    asm volatile("cp.async.cg.shared.global [%0], [%1], 16;" :: "r"(dst), "l"(src))
#define CP_COMMIT() asm volatile("cp.async.commit_group;" ::: "memory")
#define CP_WAIT(n)  asm volatile("cp.async.wait_group %0;" :: "n"(n) : "memory")

// ---------------- scratch (device globals; no allocations) ----------------
__device__ float g_S[NHEADS * NQ * NQ];                 // S (fp32); later reused as img
__device__ __nv_bfloat16 g_Qhi[NHEADS * NQ * DDIM];
__device__ __nv_bfloat16 g_Qlo[NHEADS * NQ * DDIM];
__device__ __nv_bfloat16 g_Khi[NHEADS * NQ * DDIM];
__device__ __nv_bfloat16 g_Klo[NHEADS * NQ * DDIM];
__device__ __nv_bfloat16 g_Vhi[NHEADS * NQ * DDIM];
__device__ __nv_bfloat16 g_Vlo[NHEADS * NQ * DDIM];
__device__ __nv_bfloat16 g_Vthi[NHEADS * DDIM * NQ];    // V^T [d][q]
__device__ __nv_bfloat16 g_Vtlo[NHEADS * DDIM * NQ];
__device__ __nv_bfloat16 g_Phi[NHEADS * NQ * NQ];
__device__ __nv_bfloat16 g_Plo[NHEADS * NQ * NQ];

__device__ __forceinline__ unsigned bfpack(__nv_bfloat16 a, __nv_bfloat16 b) {
    unsigned short ua = *(unsigned short*)&a, ub = *(unsigned short*)&b;
    return (unsigned)ua | ((unsigned)ub << 16);
}

// ---------------------------------------------------------------------------
// Kernel 1: fused QKV grid-conv (f32x2), emits bf16 hi/lo split outputs.
// ---------------------------------------------------------------------------
__global__ __launch_bounds__(512) void qkv_conv_kernel(
    const float* __restrict__ x,
    const float* __restrict__ wq, const float* __restrict__ bq,
    const float* __restrict__ wk, const float* __restrict__ bk,
    const float* __restrict__ wv, const float* __restrict__ bv)
{
    __shared__ float Wc[72 * 68];
    __shared__ float pat[8][8][100];

    const int conv = blockIdx.y;
    const float* wsrc = (conv == 0) ? wq : (conv == 1) ? wk : wv;
    const float* bsrc = (conv == 0) ? bq : (conv == 1) ? bk : bv;
    __nv_bfloat16* dsth = (conv == 0) ? g_Qhi : (conv == 1) ? g_Khi : g_Vhi;
    __nv_bfloat16* dstl = (conv == 0) ? g_Qlo : (conv == 1) ? g_Klo : g_Vlo;

    const int tid = threadIdx.x;
    const int s   = tid >> 6;
    const int t2  = tid & 63;
    const int cog = t2 >> 4;
    const int pt  = t2 & 15;
    const int gi  = pt >> 1;
    const int gjb = (pt & 1) * 4;
    const int co0 = cog * 16;

    u64 bias2[8];
#pragma unroll
    for (int c = 0; c < 8; c++) PK2(bias2[c], bsrc[co0 + 2 * c], bsrc[co0 + 2 * c + 1]);

    for (int i = tid; i < 8 * 8 * 100; i += 512) ((float*)pat)[i] = 0.f;

    for (int g = 0; g < 4; g++) {
        const int qbase = blockIdx.x * 32 + g * 8;
        const int sg = qbase + s;
        const int bt = sg >> 10;
        const int q  = sg & 1023;

        u64 acc2[8][4];
#pragma unroll
        for (int c = 0; c < 8; c++)
#pragma unroll
            for (int u = 0; u < 4; u++) acc2[c][u] = bias2[c];

        for (int cc = 0; cc < 8; cc++) {
            __syncthreads();
            for (int i = tid; i < 4608; i += 512) {
                const int co_s = i / 72;
                const int kl   = i - co_s * 72;
                Wc[kl * 68 + co_s] = wsrc[co_s * KCONV + cc * 72 + kl];
            }
            for (int i = tid; i < 4096; i += 512) {
                const int ss  = i & 7;
                int r = i >> 3;
                const int pgj = r & 7; r >>= 3;
                const int pgi = r & 7;
                const int cil = r >> 3;
                const int sg2 = qbase + ss;
                const int bt2 = sg2 >> 10;
                const int q2  = sg2 & 1023;
                const int hi2 = q2 >> 5, wi2 = q2 & 31;
                pat[ss][cil][(pgi + 1) * 10 + pgj + 1] =
                    x[((bt2 * CIN + cc * 8 + cil) * HH + (pgi * HG + hi2)) * WW + pgj * WG + wi2];
            }
            __syncthreads();
#pragma unroll
            for (int dy = 0; dy < 3; dy++) {
#pragma unroll
                for (int dx = 0; dx < 3; dx++) {
#pragma unroll
                    for (int cl = 0; cl < 8; cl++) {
                        const float* prow = &pat[s][cl][(gi + dy) * 10 + gjb + dx];
                        const float p0 = prow[0], p1 = prow[1], p2 = prow[2], p3 = prow[3];
                        const float* wrow = &Wc[(cl * 9 + dy * 3 + dx) * 68 + co0];
                        const ulonglong2 wA = *(const ulonglong2*)&wrow[0];
                        const ulonglong2 wB = *(const ulonglong2*)&wrow[4];
                        const ulonglong2 wC = *(const ulonglong2*)&wrow[8];
                        const ulonglong2 wD = *(const ulonglong2*)&wrow[12];
                        CFMA(0, p0) CFMA(1, p1) CFMA(2, p2) CFMA(3, p3)
                    }
                }
            }
        }
        float accf[16][4];
#pragma unroll
        for (int c = 0; c < 8; c++)
#pragma unroll
            for (int u = 0; u < 4; u++) { UNPK(accf[2 * c][u], accf[2 * c + 1][u], acc2[c][u]); }
#pragma unroll
        for (int i = 0; i < 16; i++) {
            const int co = co0 + i;
            const int n = co >> 3, cl = co & 7;
            const size_t base = ((size_t)(bt * NHD + n) * NQ + q) * DDIM + cl * 64 + pt * 4;
            __nv_bfloat16 h0 = __float2bfloat16_rn(accf[i][0]);
            __nv_bfloat16 h1 = __float2bfloat16_rn(accf[i][1]);
            __nv_bfloat16 h2 = __float2bfloat16_rn(accf[i][2]);
            __nv_bfloat16 h3 = __float2bfloat16_rn(accf[i][3]);
            uint2 vh; vh.x = bfpack(h0, h1); vh.y = bfpack(h2, h3);
            *(uint2*)&dsth[base] = vh;
            __nv_bfloat16 l0 = __float2bfloat16_rn(accf[i][0] - __bfloat162float(h0));
            __nv_bfloat16 l1 = __float2bfloat16_rn(accf[i][1] - __bfloat162float(h1));
            __nv_bfloat16 l2 = __float2bfloat16_rn(accf[i][2] - __bfloat162float(h2));
            __nv_bfloat16 l3 = __float2bfloat16_rn(accf[i][3] - __bfloat162float(h3));
            uint2 vl; vl.x = bfpack(l0, l1); vl.y = bfpack(l2, l3);
            *(uint2*)&dstl[base] = vl;
        }
    }
}

// ---------------------------------------------------------------------------
// Kernel 2: V^T transpose (bf16 hi+lo), 64x64 tiles via smem.
// ---------------------------------------------------------------------------
__global__ __launch_bounds__(256) void vt_kernel()
{
    __shared__ __nv_bfloat16 sh[64][66];
    __shared__ __nv_bfloat16 sl[64][66];
    const int tid = threadIdx.x;
    const int h  = blockIdx.z;
    const int q0 = blockIdx.y * 64;
    const int d0 = blockIdx.x * 64;
    const __nv_bfloat16* Vh = g_Vhi + (size_t)h * NQ * DDIM;
    const __nv_bfloat16* Vl = g_Vlo + (size_t)h * NQ * DDIM;
    for (int i = tid; i < 4096; i += 256) {
        const int qq = i >> 6, dd = i & 63;
        sh[qq][dd] = Vh[(size_t)(q0 + qq) * DDIM + d0 + dd];
        sl[qq][dd] = Vl[(size_t)(q0 + qq) * DDIM + d0 + dd];
    }
    __syncthreads();
    __nv_bfloat16* Th = g_Vthi + (size_t)h * DDIM * NQ;
    __nv_bfloat16* Tl = g_Vtlo + (size_t)h * DDIM * NQ;
    for (int i = tid; i < 4096; i += 256) {
        const int dd = i >> 6, qq = i & 63;
        Th[(size_t)(d0 + dd) * NQ + q0 + qq] = sh[qq][dd];
        Tl[(size_t)(d0 + dd) * NQ + q0 + qq] = sl[qq][dd];
    }
}

// ---------------------------------------------------------------------------
// HMMA GEMM core v2: 128x128 CTA tile, 8 warps (4 m x 2 n), per-warp 32x64.
// BK=16 chunks, double-buffered cp.async staging (2 stages x 4 tiles = 48KB).
// 3 split products Ah*Bh + Ah*Bl + Al*Bh with fragment reuse.
// ---------------------------------------------------------------------------
#define PADK2 24
#define TILE_EL (128 * PADK2)

struct MmaAcc { float c[2][8][4]; };

// Stage one 128x16 bf16 tile: 256 cp.async (16B), exactly 1 per thread.
__device__ __forceinline__ void stage_cp(uint32_t sbase, const __nv_bfloat16* g,
                                         size_t ld, int kc, int tid) {
    const int row = tid >> 1, seg = tid & 1;
    const uint32_t dst = sbase + (uint32_t)(row * PADK2 + seg * 8) * 2;
    const __nv_bfloat16* src = g + (size_t)row * ld + kc + seg * 8;
    CP_ASYNC16(dst, src);
}

__device__ __forceinline__ void mma_chunk16(MmaAcc& A_, uint32_t aAh, uint32_t aAl,
                                            uint32_t aBh, uint32_t aBl,
                                            int wm, int wn, int lane) {
    const int lr = lane & 15;
    const int lc = (lane >> 4) * 8;
    uint32_t ah[2][4], al[2][4];
#pragma unroll
    for (int mf = 0; mf < 2; mf++) {
        const uint32_t off = (uint32_t)((wm * 32 + mf * 16 + lr) * PADK2 + lc) * 2;
        LDSM4(ah[mf][0], ah[mf][1], ah[mf][2], ah[mf][3], aAh + off);
        LDSM4(al[mf][0], al[mf][1], al[mf][2], al[mf][3], aAl + off);
    }
#pragma unroll
    for (int nq = 0; nq < 4; nq++) {
        const uint32_t boff = (uint32_t)((wn * 64 + nq * 16 + lr) * PADK2 + lc) * 2;
        uint32_t bh0, bh1, bh2, bh3, bl0, bl1, bl2, bl3;
        LDSM4(bh0, bh1, bh2, bh3, aBh + boff);
        LDSM4(bl0, bl1, bl2, bl3, aBl + boff);
#pragma unroll
        for (int mf = 0; mf < 2; mf++) {
            MMA16816(A_.c[mf][nq * 2 + 0], ah[mf], bh0, bh2);
            MMA16816(A_.c[mf][nq * 2 + 1], ah[mf], bh1, bh3);
            MMA16816(A_.c[mf][nq * 2 + 0], ah[mf], bl0, bl2);
            MMA16816(A_.c[mf][nq * 2 + 1], ah[mf], bl1, bl3);
            MMA16816(A_.c[mf][nq * 2 + 0], al[mf], bh0, bh2);
            MMA16816(A_.c[mf][nq * 2 + 1], al[mf], bh1, bh3);
        }
    }
}

// ---------------------------------------------------------------------------
// Kernel 3: qk via HMMA. S = scale * (Qhi+Qlo)@(Khi+Klo)^T (lo*lo dropped).
// ---------------------------------------------------------------------------
__global__ __launch_bounds__(256) void qk_mma_kernel()
{
    __shared__ __nv_bfloat16 smb[2][4][TILE_EL];   // [stage][Ah,Al,Bh,Bl]

    const int tid = threadIdx.x, wid = tid >> 5, lane = tid & 31;
    const int wm = wid & 3, wn = wid >> 2;
    const int h = blockIdx.z, m0 = blockIdx.y * 128, n0 = blockIdx.x * 128;

    const __nv_bfloat16* src[4] = {
        g_Qhi + (size_t)h * NQ * DDIM + (size_t)m0 * DDIM,
        g_Qlo + (size_t)h * NQ * DDIM + (size_t)m0 * DDIM,
        g_Khi + (size_t)h * NQ * DDIM + (size_t)n0 * DDIM,
        g_Klo + (size_t)h * NQ * DDIM + (size_t)n0 * DDIM };

    uint32_t sb[2][4];
#pragma unroll
    for (int st = 0; st < 2; st++)
#pragma unroll
        for (int t = 0; t < 4; t++) sb[st][t] = smem_u32(smb[st][t]);

    MmaAcc acc;
#pragma unroll
    for (int mf = 0; mf < 2; mf++)
#pragma unroll
        for (int nf = 0; nf < 8; nf++)
#pragma unroll
            for (int e = 0; e < 4; e++) acc.c[mf][nf][e] = 0.f;

    const int NCH = DDIM / 16;
#pragma unroll 1
    for (int t = 0; t < 4; t++) stage_cp(sb[0][t], src[t], DDIM, 0, tid);
    CP_COMMIT();

    for (int c = 0; c < NCH; c++) {
        const int cur = c & 1;
        if (c + 1 < NCH) {
#pragma unroll 1
            for (int t = 0; t < 4; t++)
                stage_cp(sb[cur ^ 1][t], src[t], DDIM, (c + 1) * 16, tid);
            CP_COMMIT();
            CP_WAIT(1);
        } else {
            CP_WAIT(0);
        }
        __syncthreads();
        mma_chunk16(acc, sb[cur][0], sb[cur][1], sb[cur][2], sb[cur][3], wm, wn, lane);
        __syncthreads();
    }

    float* C = g_S + (size_t)h * NQ * NQ;
    const int r = lane >> 2, c2 = (lane & 3) * 2;
#pragma unroll
    for (int mf = 0; mf < 2; mf++) {
        const int m = m0 + wm * 32 + mf * 16 + r;
#pragma unroll
        for (int nf = 0; nf < 8; nf++) {
            const int n = n0 + wn * 64 + nf * 8 + c2;
            float2 v0 = make_float2(acc.c[mf][nf][0] * ATT_SCALE, acc.c[mf][nf][1] * ATT_SCALE);
            float2 v1 = make_float2(acc.c[mf][nf][2] * ATT_SCALE, acc.c[mf][nf][3] * ATT_SCALE);
            *(float2*)&C[(size_t)m * NQ + n] = v0;
            *(float2*)&C[(size_t)(m + 8) * NQ + n] = v1;
        }
    }
}

// ---------------------------------------------------------------------------
// Kernel 4: row softmax over g_S; writes P as bf16 hi/lo split.
// ---------------------------------------------------------------------------
__global__ __launch_bounds__(256) void softmax_kernel()
{
    __shared__ float redm[8];
    __shared__ float reds[8];
    const int tid = threadIdx.x;
    for (int r = 0; r < 4; r++) {
        const size_t row = (size_t)blockIdx.x * 4 + r;
        float* S = g_S + row * NQ;
        float v0 = S[tid], v1 = S[tid + 256], v2 = S[tid + 512], v3 = S[tid + 768];
        float m = fmaxf(fmaxf(v0, v1), fmaxf(v2, v3));
#pragma unroll
        for (int o = 16; o > 0; o >>= 1) m = fmaxf(m, __shfl_xor_sync(0xffffffffu, m, o));
        if ((tid & 31) == 0) redm[tid >> 5] = m;
        __syncthreads();
        m = redm[0];
#pragma unroll
        for (int i = 1; i < 8; i++) m = fmaxf(m, redm[i]);
        v0 = __expf(v0 - m); v1 = __expf(v1 - m); v2 = __expf(v2 - m); v3 = __expf(v3 - m);
        float sum = v0 + v1 + v2 + v3;
#pragma unroll
        for (int o = 16; o > 0; o >>= 1) sum += __shfl_xor_sync(0xffffffffu, sum, o);
        if ((tid & 31) == 0) reds[tid >> 5] = sum;
        __syncthreads();
        sum = 0.f;
#pragma unroll
        for (int i = 0; i < 8; i++) sum += reds[i];
        const float inv = 1.0f / sum;
        __nv_bfloat16* Ph = g_Phi + row * NQ;
        __nv_bfloat16* Pl = g_Plo + row * NQ;
        const float p[4] = {v0 * inv, v1 * inv, v2 * inv, v3 * inv};
#pragma unroll
        for (int k = 0; k < 4; k++) {
            const int idx = tid + k * 256;
            __nv_bfloat16 hh = __float2bfloat16_rn(p[k]);
            Ph[idx] = hh;
            Pl[idx] = __float2bfloat16_rn(p[k] - __bfloat162float(hh));
        }
        __syncthreads();
    }
}

// ---------------------------------------------------------------------------
// Kernel 5: pv via HMMA. Y = (Phi+Plo)@(Vt_hi+Vt_lo)^T (lo*lo dropped).
// Epilogue: grid2im scatter into img (aliased on g_S, dead after softmax).
// ---------------------------------------------------------------------------
__global__ __launch_bounds__(256) void pv_mma_kernel()
{
    __shared__ __nv_bfloat16 smb[2][4][TILE_EL];

    const int tid = threadIdx.x, wid = tid >> 5, lane = tid & 31;
    const int wm = wid & 3, wn = wid >> 2;
    const int h = blockIdx.z, m0 = blockIdx.y * 128, n0 = blockIdx.x * 128;

    const __nv_bfloat16* src[4] = {
        g_Phi + (size_t)h * NQ * NQ + (size_t)m0 * NQ,
        g_Plo + (size_t)h * NQ * NQ + (size_t)m0 * NQ,
        g_Vthi + (size_t)h * DDIM * NQ + (size_t)n0 * NQ,
        g_Vtlo + (size_t)h * DDIM * NQ + (size_t)n0 * NQ };

    uint32_t sb[2][4];
#pragma unroll
    for (int st = 0; st < 2; st++)
#pragma unroll
        for (int t = 0; t < 4; t++) sb[st][t] = smem_u32(smb[st][t]);

    MmaAcc acc;
#pragma unroll
    for (int mf = 0; mf < 2; mf++)
#pragma unroll
        for (int nf = 0; nf < 8; nf++)
#pragma unroll
            for (int e = 0; e < 4; e++) acc.c[mf][nf][e] = 0.f;

    const int NCH = NQ / 16;
#pragma unroll 1
    for (int t = 0; t < 4; t++) stage_cp(sb[0][t], src[t], NQ, 0, tid);
    CP_COMMIT();

    for (int c = 0; c < NCH; c++) {
        const int cur = c & 1;
        if (c + 1 < NCH) {
#pragma unroll 1
            for (int t = 0; t < 4; t++)
                stage_cp(sb[cur ^ 1][t], src[t], NQ, (c + 1) * 16, tid);
            CP_COMMIT();
            CP_WAIT(1);
        } else {
            CP_WAIT(0);
        }
        __syncthreads();
        mma_chunk16(acc, sb[cur][0], sb[cur][1], sb[cur][2], sb[cur][3], wm, wn, lane);
        __syncthreads();
    }

    float* img = g_S;   // alias: g_S dead after softmax
    const int bt = h >> 3, nh = h & 7;
    const int r = lane >> 2, c2 = (lane & 3) * 2;
#pragma unroll
    for (int mf = 0; mf < 2; mf++) {
#pragma unroll
        for (int half = 0; half < 2; half++) {
            const int q  = m0 + wm * 32 + mf * 16 + half * 8 + r;
            const int hi = q >> 5, wi = q & 31;
#pragma unroll
            for (int nf = 0; nf < 8; nf++) {
#pragma unroll
                for (int e = 0; e < 2; e++) {
                    const int d = n0 + wn * 64 + nf * 8 + c2 + e;
                    const int cl = d >> 6, rr = d & 63;
                    const int pgi = rr >> 3, pgj = rr & 7;
                    const int co = nh * 8 + cl;
                    img[((bt * COUT + co) * HH + (pgi * HG + hi)) * WW + (pgj * WG + wi)] =
                        acc.c[mf][nf][half * 2 + e];
                }
            }
        }
    }
}

// ---------------------------------------------------------------------------
// Kernel 6: out = img + conv3x3(img, wo) + bo ; 16 co per thread, f32x2.
// img aliased on g_S.
// ---------------------------------------------------------------------------
__global__ __launch_bounds__(256) void oconv_kernel(
    const float* __restrict__ wo, const float* __restrict__ bo,
    float* __restrict__ out)
{
    __shared__ float patch[8 * 18 * 34];
    __shared__ float Ws[72 * 16];

    const int bz  = blockIdx.z;
    const int bt  = bz >> 2;
    const int co0 = (bz & 3) * 16;
    const int h0  = blockIdx.y * 16;
    const int w0  = blockIdx.x * 32;

    const int tid = threadIdx.x;
    const int th  = tid >> 4;
    const int tw  = tid & 15;

    u64 acc2[8][2];
#pragma unroll
    for (int c = 0; c < 8; c++) { acc2[c][0] = 0ull; acc2[c][1] = 0ull; }

    const float* img = g_S + (size_t)bt * COUT * HH * WW;

    for (int cc = 0; cc < 8; cc++) {
        const int ci0 = cc * 8;
        __syncthreads();
        for (int i = tid; i < 8 * 18 * 34; i += 256) {
            const int ci = i / 612;
            const int rem = i - ci * 612;
            const int r = rem / 34;
            const int c = rem - r * 34;
            const int gh = h0 - 1 + r, gw = w0 - 1 + c;
            float v = 0.f;
            if (gh >= 0 && gh < HH && gw >= 0 && gw < WW)
                v = img[((ci0 + ci) * HH + gh) * WW + gw];
            patch[i] = v;
        }
        for (int i = tid; i < 72 * 16; i += 256) {
            const int co = i & 15;
            const int rem = i >> 4;
            Ws[rem * 16 + co] = wo[(co0 + co) * KCONV + ci0 * 9 + rem];
        }
        __syncthreads();
#pragma unroll
        for (int dy = 0; dy < 3; dy++) {
#pragma unroll
            for (int dx = 0; dx < 3; dx++) {
#pragma unroll
                for (int ci = 0; ci < 8; ci++) {
                    const float p0 = patch[ci * 612 + (th + dy) * 34 + (tw + dx)];
                    const float p1 = patch[ci * 612 + (th + dy) * 34 + (tw + 16 + dx)];
                    const float* wrow = &Ws[(ci * 9 + dy * 3 + dx) * 16];
                    const ulonglong2 wA = *(const ulonglong2*)&wrow[0];
                    const ulonglong2 wB = *(const ulonglong2*)&wrow[4];
                    const ulonglong2 wC = *(const ulonglong2*)&wrow[8];
                    const ulonglong2 wD = *(const ulonglong2*)&wrow[12];
                    CFMA(0, p0) CFMA(1, p1)
                }
            }
        }
    }
#pragma unroll
    for (int c = 0; c < 8; c++) {
        float a00, a10, a01, a11;
        UNPK(a00, a10, acc2[c][0]);
        UNPK(a01, a11, acc2[c][1]);
        const int coA = co0 + 2 * c;
        const int coB = coA + 1;
        const float bA = bo[coA], bB = bo[coB];
        const size_t oA = ((size_t)(bt * COUT + coA) * HH + (h0 + th)) * WW + (w0 + tw);
        const size_t oB = ((size_t)(bt * COUT + coB) * HH + (h0 + th)) * WW + (w0 + tw);
        out[oA]      = a00 + bA + img[(coA * HH + h0 + th) * WW + w0 + tw];
        out[oA + 16] = a01 + bA + img[(coA * HH + h0 + th) * WW + w0 + tw + 16];
        out[oB]      = a10 + bB + img[(coB * HH + h0 + th) * WW + w0 + tw];
        out[oB + 16] = a11 + bB + img[(coB * HH + h0 + th) * WW + w0 + tw + 16];
    }
}

// ---------------------------------------------------------------------------
extern "C" void kernel_launch(void* const* d_in, const int* in_sizes, int n_in,
                              void* d_out, int out_size)
{
    (void)in_sizes; (void)n_in; (void)out_size;
    const float* x  = (const float*)d_in[0];
    const float* wq = (const float*)d_in[1];
    const float* bq = (const float*)d_in[2];
    const float* wk = (const float*)d_in[3];
    const float* bk = (const float*)d_in[4];
    const float* wv = (const float*)d_in[5];
    const float* bv = (const float*)d_in[6];
    const float* wo = (const float*)d_in[7];
    const float* bo = (const float*)d_in[8];
    float* out = (float*)d_out;

    qkv_conv_kernel<<<dim3(256, 3), 512>>>(x, wq, bq, wk, bk, wv, bv);
    vt_kernel<<<dim3(8, 16, 64), 256>>>();
    qk_mma_kernel<<<dim3(8, 8, 64), 256>>>();
    softmax_kernel<<<16384, 256>>>();
    pv_mma_kernel<<<dim3(4, 8, 64), 256>>>();
    oconv_kernel<<<dim3(8, 16, 32), 256>>>(wo, bo, out);
}